// round 7
// baseline (speedup 1.0000x reference)
#include <cuda_runtime.h>
#include <cuda_fp16.h>
#include <cstdint>

#define BATCH 4
#define SEQ   4096
#define DM    1024
#define DK    64
#define ROWS  (BATCH*SEQ)
#define NOUT  192           // Q|K|V concat

#define BM 64               // queries per CTA (flash)
#define BN 64               // kv per tile
#define NT (SEQ/BN)

// ---------------------------------------------------------------------------
// Global scratch (fp16). Q pre-scaled by (1/8)*log2(e) (folded into W at prep).
// ---------------------------------------------------------------------------
__device__ __half g_Qf [ROWS*DK];
__device__ __half g_Kf [ROWS*DK];
__device__ __half g_Vt [DK*ROWS];      // transposed [d][row]
__device__ __half g_WHh[NOUT*DM];      // W^T [n][k], fp16 hi
__device__ __half g_WHl[NOUT*DM];      // fp16 lo (residual)
__device__ float  g_bias[NOUT];

// ---------------------------------------------------------------------------
// Helpers (base-target PTX only)
// ---------------------------------------------------------------------------
__device__ __forceinline__ uint32_t smem_to_u32(const void* p) {
    uint32_t a;
    asm("{ .reg .u64 t; cvta.to.shared.u64 t, %1; cvt.u32.u64 %0, t; }" : "=r"(a) : "l"(p));
    return a;
}
__device__ __forceinline__ float fast_exp2(float x) {
    float y; asm("ex2.approx.ftz.f32 %0, %1;" : "=f"(y) : "f"(x)); return y;
}
__device__ __forceinline__ void cpasync16(uint32_t dst, const void* src) {
    asm volatile("cp.async.cg.shared.global [%0], [%1], 16;" :: "r"(dst), "l"(src));
}
#define CP_COMMIT() asm volatile("cp.async.commit_group;" ::: "memory")
#define CP_WAIT0()  asm volatile("cp.async.wait_group 0;" ::: "memory")
#define CP_WAIT1()  asm volatile("cp.async.wait_group 1;" ::: "memory")

__device__ __forceinline__ void ldsm_x4(uint32_t* r, uint32_t a) {
    asm volatile("ldmatrix.sync.aligned.m8n8.x4.shared.b16 {%0,%1,%2,%3}, [%4];"
        : "=r"(r[0]), "=r"(r[1]), "=r"(r[2]), "=r"(r[3]) : "r"(a));
}
__device__ __forceinline__ void mma_f16(float* d, const uint32_t* a,
                                        uint32_t b0, uint32_t b1) {
    asm volatile("mma.sync.aligned.m16n8k16.row.col.f32.f16.f16.f32 "
        "{%0,%1,%2,%3}, {%4,%5,%6,%7}, {%8,%9}, {%0,%1,%2,%3};"
        : "+f"(d[0]), "+f"(d[1]), "+f"(d[2]), "+f"(d[3])
        : "r"(a[0]), "r"(a[1]), "r"(a[2]), "r"(a[3]), "r"(b0), "r"(b1));
}
__device__ __forceinline__ uint32_t pack_h2(float x, float y) {
    __half2 t = __floats2half2_rn(x, y);
    return *reinterpret_cast<uint32_t*>(&t);
}

#define RSTRIDE 144u        // padded 16-bit row stride in bytes (72 elems)

// ---------------------------------------------------------------------------
// Prep: W^T fp16 hi/lo (QSC folded into Q cols), bias. 256 CTAs x 4 k-cols.
// ---------------------------------------------------------------------------
__global__ __launch_bounds__(256) void prep_w(
    const float* __restrict__ WQ, const float* __restrict__ bQ,
    const float* __restrict__ WK, const float* __restrict__ bK,
    const float* __restrict__ WV, const float* __restrict__ bV)
{
    __shared__ float s[NOUT][5];
    const float QSC = 0.125f * 1.4426950408889634f;
    const int tid = threadIdx.x;
    const int k0  = blockIdx.x * 4;

    #pragma unroll
    for (int i = 0; i < 3; i++) {
        int idx = tid + i * 256;          // 0..767, n fast
        int k = idx / NOUT, n = idx - k * NOUT;
        float w;
        if (n < 64)       w = WQ[(size_t)(k0 + k) * DK + n] * QSC;
        else if (n < 128) w = WK[(size_t)(k0 + k) * DK + (n - 64)];
        else              w = WV[(size_t)(k0 + k) * DK + (n - 128)];
        s[n][k] = w;
    }
    __syncthreads();
    if (tid < NOUT) {
        __half hi[4], lo[4];
        #pragma unroll
        for (int k = 0; k < 4; k++) {
            float w = s[tid][k];
            hi[k] = __float2half_rn(w);
            lo[k] = __float2half_rn(w - __half2float(hi[k]));
        }
        *(uint2*)(g_WHh + (size_t)tid * DM + k0) = *(uint2*)hi;
        *(uint2*)(g_WHl + (size_t)tid * DM + k0) = *(uint2*)lo;
    }
    if (blockIdx.x == 0 && tid < NOUT) {
        float bb;
        if (tid < 64)       bb = bQ[tid] * QSC;
        else if (tid < 128) bb = bK[tid - 64];
        else                bb = bV[tid - 128];
        g_bias[tid] = bb;
    }
}

// ---------------------------------------------------------------------------
// Tensorized projection: grid (rows/128, 2). Each CTA: 128 rows x 96 n-cols.
// X fp16 single, W fp16 hi/lo (2 products). 8 warps x 16 rows x 96 n.
// ---------------------------------------------------------------------------
#define P_XB    0u            // X bufs: buf*18432 (128 rows)
#define P_WB    36864u        // W bufs: buf*27648 ; WH +0, WL +13824
#define P_BIAS  92160u        // 96 floats
#define P_TOTAL 92544u

__global__ __launch_bounds__(256, 2) void proj_tc(const float* __restrict__ X)
{
    extern __shared__ char smem[];
    const uint32_t sb = smem_to_u32(smem);
    const int tid  = threadIdx.x;
    const int wid  = tid >> 5;
    const int lane = tid & 31;
    const int gid  = lane >> 2;
    const int tq   = lane & 3;
    const int r0g  = blockIdx.x * 128;
    const int ny   = blockIdx.y;          // n half: 0 -> n 0..95, 1 -> 96..191
    const int nbase = ny * 96;

    float* biass = (float*)(smem + P_BIAS);
    if (tid < 96) biass[tid] = g_bias[nbase + tid];

    const int xrow  = tid >> 1;
    const int xhalf = tid & 1;
    const float* Xrow = X + (size_t)(r0g + xrow) * DM + xhalf * 32;
    const uint32_t xso = P_XB + (uint32_t)xrow * RSTRIDE + (uint32_t)xhalf * 64;

    // prologue: W chunk0 + X chunk0
    {
        #pragma unroll
        for (int t = 0; t < 6; t++) {
            int idx = tid + t * 256;          // 0..1535
            int arr = (idx >= 768);
            int i   = idx - arr * 768;
            int row = i >> 3, c = i & 7;
            const __half* src = (arr ? g_WHl : g_WHh) + (size_t)(nbase + row) * DM + c * 8;
            cpasync16(sb + P_WB + (uint32_t)arr * 13824u + (uint32_t)row * RSTRIDE + c * 16, src);
        }
        CP_COMMIT();
        float4 xr[8];
        #pragma unroll
        for (int i = 0; i < 8; i++) xr[i] = *(const float4*)(Xrow + 4 * i);
        #pragma unroll
        for (int i = 0; i < 8; i++) {
            uint2 v;
            v.x = pack_h2(xr[i].x, xr[i].y);
            v.y = pack_h2(xr[i].z, xr[i].w);
            *(uint2*)(smem + xso + 8 * i) = v;
        }
        CP_WAIT0();
        __syncthreads();
    }

    float O[12][4];
    #pragma unroll
    for (int n = 0; n < 12; n++)
        #pragma unroll
        for (int c = 0; c < 4; c++) O[n][c] = 0.f;

    const uint32_t aoff = (uint32_t)(wid * 16 + (lane & 15)) * RSTRIDE + (uint32_t)(lane >> 4) * 16;
    const uint32_t boff = (uint32_t)(((lane >> 4) & 1) * 8 + (lane & 7)) * RSTRIDE
                        + (uint32_t)((lane >> 3) & 1) * 16;

    for (int ch = 0; ch < 16; ch++) {
        const uint32_t XB = sb + P_XB + (uint32_t)(ch & 1) * 18432u;
        const uint32_t WB = sb + P_WB + (uint32_t)(ch & 1) * 27648u;
        const int nxt = ch + 1;
        float4 xr[8];

        if (nxt < 16) {
            const uint32_t WB1 = sb + P_WB + (uint32_t)(nxt & 1) * 27648u;
            #pragma unroll
            for (int t = 0; t < 6; t++) {
                int idx = tid + t * 256;
                int arr = (idx >= 768);
                int i   = idx - arr * 768;
                int row = i >> 3, c = i & 7;
                const __half* src = (arr ? g_WHl : g_WHh)
                                  + (size_t)(nbase + row) * DM + nxt * 64 + c * 8;
                cpasync16(WB1 + (uint32_t)arr * 13824u + (uint32_t)row * RSTRIDE + c * 16, src);
            }
            CP_COMMIT();
            #pragma unroll
            for (int i = 0; i < 8; i++) xr[i] = *(const float4*)(Xrow + nxt * 64 + 4 * i);
        }

        #pragma unroll
        for (int kc = 0; kc < 4; kc++) {
            uint32_t ah[4];
            ldsm_x4(ah, XB + aoff + kc * 32);
            #pragma unroll
            for (int p = 0; p < 6; p++) {
                uint32_t wh[4], wl[4];
                ldsm_x4(wh, WB + boff + (uint32_t)p * (16 * RSTRIDE) + kc * 32);
                mma_f16(O[2*p],   ah, wh[0], wh[1]);
                mma_f16(O[2*p+1], ah, wh[2], wh[3]);
                ldsm_x4(wl, WB + 13824u + boff + (uint32_t)p * (16 * RSTRIDE) + kc * 32);
                mma_f16(O[2*p],   ah, wl[0], wl[1]);
                mma_f16(O[2*p+1], ah, wl[2], wl[3]);
            }
        }

        if (nxt < 16) {
            const uint32_t xo = xso + (uint32_t)(nxt & 1) * 18432u;
            #pragma unroll
            for (int i = 0; i < 8; i++) {
                uint2 v;
                v.x = pack_h2(xr[i].x, xr[i].y);
                v.y = pack_h2(xr[i].z, xr[i].w);
                *(uint2*)(smem + xo + 8 * i) = v;
            }
            CP_WAIT0();
        }
        __syncthreads();
    }

    // ---- epilogue: +bias, emit fp16 flash operands
    const int rr0 = r0g + wid * 16 + gid;
    const int rr1 = rr0 + 8;
    #pragma unroll
    for (int nt = 0; nt < 12; nt++) {
        const int cl = nt * 8 + 2 * tq;        // local n
        const int cg = nbase + cl;             // global n
        const float b0 = biass[cl], b1 = biass[cl + 1];
        float v00 = O[nt][0] + b0, v01 = O[nt][1] + b1;
        float v10 = O[nt][2] + b0, v11 = O[nt][3] + b1;
        if (cg < 64) {
            *(__half2*)(g_Qf + (size_t)rr0 * DK + cg) = __floats2half2_rn(v00, v01);
            *(__half2*)(g_Qf + (size_t)rr1 * DK + cg) = __floats2half2_rn(v10, v11);
        } else if (cg < 128) {
            const int ck = cg - 64;
            *(__half2*)(g_Kf + (size_t)rr0 * DK + ck) = __floats2half2_rn(v00, v01);
            *(__half2*)(g_Kf + (size_t)rr1 * DK + ck) = __floats2half2_rn(v10, v11);
        } else {
            const int d0 = cg - 128, d1 = d0 + 1;
            g_Vt[(size_t)d0 * ROWS + rr0] = __float2half_rn(v00);
            g_Vt[(size_t)d1 * ROWS + rr0] = __float2half_rn(v01);
            g_Vt[(size_t)d0 * ROWS + rr1] = __float2half_rn(v10);
            g_Vt[(size_t)d1 * ROWS + rr1] = __float2half_rn(v11);
        }
    }
}

// ---------------------------------------------------------------------------
// Flash attention: 128-thread CTAs, BM=64, interleaved QK/exp/PV per 16 keys.
// ---------------------------------------------------------------------------
#define SM_QF   0u
#define SM_BUF0 9216u
#define SM_BUFSZ 18432u      // K +0 (9216), V +9216
#define SM_TOTAL (SM_BUF0 + 3*SM_BUFSZ)

__device__ __forceinline__ void load_kv(uint32_t dst, int tid, size_t bSE, int j0)
{
    #pragma unroll
    for (int t = 0; t < 4; t++) {
        int i = tid + t * 128;            // 0..511 : K 64 rows x 8 chunks
        int row = i >> 3, c = i & 7;
        cpasync16(dst + row * RSTRIDE + c * 16,
                  g_Kf + (bSE + j0 + row) * DK + c * 8);
    }
    #pragma unroll
    for (int t = 0; t < 4; t++) {
        int i = tid + t * 128;            // V: [d][key]
        int d = i >> 3, c = i & 7;
        cpasync16(dst + 9216u + d * RSTRIDE + c * 16,
                  g_Vt + (size_t)d * ROWS + bSE + j0 + c * 8);
    }
}

__global__ __launch_bounds__(128, 3) void flash_mma(float* __restrict__ out)
{
    extern __shared__ char smem[];
    const uint32_t sb = smem_to_u32(smem);
    const int tid  = threadIdx.x;
    const int wid  = tid >> 5;
    const int lane = tid & 31;
    const int gid  = lane >> 2;
    const int tq   = lane & 3;

    const int b  = blockIdx.y;
    const int q0 = blockIdx.x * BM;
    const size_t bSE = (size_t)b * SEQ;

    // prologue: group0 = {Q, tile0}, group1 = {tile1}
    #pragma unroll
    for (int t = 0; t < 4; t++) {
        int idx = tid + t * 128;          // 64 rows x 8 chunks
        int row = idx >> 3, c = idx & 7;
        cpasync16(sb + SM_QF + row * RSTRIDE + c * 16,
                  g_Qf + (bSE + q0 + row) * DK + c * 8);
    }
    load_kv(sb + SM_BUF0, tid, bSE, 0);
    CP_COMMIT();
    load_kv(sb + SM_BUF0 + SM_BUFSZ, tid, bSE, BN);
    CP_COMMIT();
    CP_WAIT1();
    __syncthreads();

    uint32_t qf[4][4];
    {
        uint32_t aoff = (uint32_t)(wid * 16 + (lane & 15)) * RSTRIDE + (uint32_t)(lane >> 4) * 16;
        #pragma unroll
        for (int kc = 0; kc < 4; kc++)
            ldsm_x4(qf[kc], sb + SM_QF + aoff + kc * 32);
    }

    float O[8][4];
    #pragma unroll
    for (int i = 0; i < 8; i++)
        #pragma unroll
        for (int c = 0; c < 4; c++) O[i][c] = 0.f;
    float lsum0 = 0.f, lsum1 = 0.f;

    const uint32_t boff = (uint32_t)(((lane >> 4) & 1) * 8 + (lane & 7)) * RSTRIDE
                        + (uint32_t)((lane >> 3) & 1) * 16;

    const uint32_t bufs[3] = {sb + SM_BUF0, sb + SM_BUF0 + SM_BUFSZ, sb + SM_BUF0 + 2*SM_BUFSZ};

    for (int j = 0; j < NT; j++) {
        const uint32_t buf = bufs[j % 3];

        // interleaved per 16-key group: QK -> exp -> PV
        #pragma unroll
        for (int np = 0; np < 4; np++) {
            // ---- S tiles for keys [16*np, 16*np+16)
            float S0[4] = {0.f, 0.f, 0.f, 0.f};
            float S1[4] = {0.f, 0.f, 0.f, 0.f};
            #pragma unroll
            for (int kc = 0; kc < 4; kc++) {
                uint32_t kr[4];
                ldsm_x4(kr, buf + boff + (uint32_t)np * (16 * RSTRIDE) + kc * 32);
                mma_f16(S0, qf[kc], kr[0], kr[1]);
                mma_f16(S1, qf[kc], kr[2], kr[3]);
            }

            // ---- softmax: p = exp2(s) (scale folded into Q)
            float p00 = fast_exp2(S0[0]), p01 = fast_exp2(S0[1]);
            float p02 = fast_exp2(S0[2]), p03 = fast_exp2(S0[3]);
            float p10 = fast_exp2(S1[0]), p11 = fast_exp2(S1[1]);
            float p12 = fast_exp2(S1[2]), p13 = fast_exp2(S1[3]);
            lsum0 += p00 + p01 + p10 + p11;
            lsum1 += p02 + p03 + p12 + p13;
            uint32_t Pf[4];
            Pf[0] = pack_h2(p00, p01);
            Pf[1] = pack_h2(p02, p03);
            Pf[2] = pack_h2(p10, p11);
            Pf[3] = pack_h2(p12, p13);

            // ---- O += P[:,16np:16np+16] @ V
            #pragma unroll
            for (int vd = 0; vd < 4; vd++) {
                uint32_t vr[4];
                ldsm_x4(vr, buf + 9216u + boff + (uint32_t)vd * (16 * RSTRIDE) + np * 32);
                mma_f16(O[2*vd],   Pf, vr[0], vr[1]);
                mma_f16(O[2*vd+1], Pf, vr[2], vr[3]);
            }
        }

        // ---- pipeline: prefetch j+2, ensure j+1 arrived, one barrier
        if (j + 2 < NT) {
            load_kv(bufs[(j + 2) % 3], tid, bSE, (j + 2) * BN);
            CP_COMMIT();
            CP_WAIT1();
        } else {
            CP_WAIT0();
        }
        __syncthreads();
    }

    // ---- epilogue
    lsum0 += __shfl_xor_sync(0xffffffffu, lsum0, 1);
    lsum0 += __shfl_xor_sync(0xffffffffu, lsum0, 2);
    lsum1 += __shfl_xor_sync(0xffffffffu, lsum1, 1);
    lsum1 += __shfl_xor_sync(0xffffffffu, lsum1, 2);
    const float inv0 = 1.f / lsum0;
    const float inv1 = 1.f / lsum1;

    const int row0 = q0 + wid * 16 + gid;
    float* o0 = out + (bSE + row0) * DK;
    float* o1 = o0 + 8 * DK;
    #pragma unroll
    for (int nt = 0; nt < 8; nt++) {
        const int col = nt * 8 + 2 * tq;
        *(float2*)(o0 + col) = make_float2(O[nt][0] * inv0, O[nt][1] * inv0);
        *(float2*)(o1 + col) = make_float2(O[nt][2] * inv1, O[nt][3] * inv1);
    }
}

// ---------------------------------------------------------------------------
extern "C" void kernel_launch(void* const* d_in, const int* in_sizes, int n_in,
                              void* d_out, int out_size)
{
    const float* X  = (const float*)d_in[0];
    // d_in[1] cultural_embedding, d_in[8..10] WC,bC,lam: softmax-invariant -> unused
    const float* WQ = (const float*)d_in[2];
    const float* bQ = (const float*)d_in[3];
    const float* WK = (const float*)d_in[4];
    const float* bK = (const float*)d_in[5];
    const float* WV = (const float*)d_in[6];
    const float* bV = (const float*)d_in[7];
    float* out = (float*)d_out;

    cudaFuncSetAttribute(proj_tc,   cudaFuncAttributeMaxDynamicSharedMemorySize, P_TOTAL);
    cudaFuncSetAttribute(flash_mma, cudaFuncAttributeMaxDynamicSharedMemorySize, SM_TOTAL);

    prep_w<<<DM / 4, 256>>>(WQ, bQ, WK, bK, WV, bV);
    proj_tc<<<dim3(ROWS / 128, 2), 256, P_TOTAL>>>(X);
    flash_mma<<<dim3(SEQ / BM, BATCH), 128, SM_TOTAL>>>(out);
}

// round 8
// speedup vs baseline: 1.0872x; 1.0872x over previous
#include <cuda_runtime.h>
#include <cuda_fp16.h>
#include <cstdint>

#define BATCH 4
#define SEQ   4096
#define DM    1024
#define DK    64
#define ROWS  (BATCH*SEQ)
#define NOUT  192           // Q|K|V concat

#define BM 128              // queries per CTA (flash)
#define BN 64               // kv per tile
#define NT (SEQ/BN)         // 64 tiles total
#define NZ 2                // KV splits
#define NTZ (NT/NZ)         // 32 tiles per split

// ---------------------------------------------------------------------------
// Global scratch (fp16 operands; fp32 partials for split-KV combine).
// ---------------------------------------------------------------------------
__device__ __half g_Qf [ROWS*DK];
__device__ __half g_Kf [ROWS*DK];
__device__ __half g_Vt [DK*ROWS];      // transposed [d][row]
__device__ __half g_WHh[NOUT*DM];      // W^T [n][k], fp16 hi
__device__ __half g_WHl[NOUT*DM];      // fp16 lo (residual)
__device__ float  g_bias[NOUT];
__device__ float  g_Op[NZ*ROWS*DK];    // unnormalized O partials
__device__ float  g_lp[NZ*ROWS];       // row-sum partials

// ---------------------------------------------------------------------------
// Helpers (base-target PTX only)
// ---------------------------------------------------------------------------
__device__ __forceinline__ uint32_t smem_to_u32(const void* p) {
    uint32_t a;
    asm("{ .reg .u64 t; cvta.to.shared.u64 t, %1; cvt.u32.u64 %0, t; }" : "=r"(a) : "l"(p));
    return a;
}
__device__ __forceinline__ float fast_exp2(float x) {
    float y; asm("ex2.approx.ftz.f32 %0, %1;" : "=f"(y) : "f"(x)); return y;
}
__device__ __forceinline__ void cpasync16(uint32_t dst, const void* src) {
    asm volatile("cp.async.cg.shared.global [%0], [%1], 16;" :: "r"(dst), "l"(src));
}
#define CP_COMMIT() asm volatile("cp.async.commit_group;" ::: "memory")
#define CP_WAIT0()  asm volatile("cp.async.wait_group 0;" ::: "memory")
#define CP_WAIT1()  asm volatile("cp.async.wait_group 1;" ::: "memory")

__device__ __forceinline__ void ldsm_x4(uint32_t* r, uint32_t a) {
    asm volatile("ldmatrix.sync.aligned.m8n8.x4.shared.b16 {%0,%1,%2,%3}, [%4];"
        : "=r"(r[0]), "=r"(r[1]), "=r"(r[2]), "=r"(r[3]) : "r"(a));
}
__device__ __forceinline__ void mma_f16(float* d, const uint32_t* a,
                                        uint32_t b0, uint32_t b1) {
    asm volatile("mma.sync.aligned.m16n8k16.row.col.f32.f16.f16.f32 "
        "{%0,%1,%2,%3}, {%4,%5,%6,%7}, {%8,%9}, {%0,%1,%2,%3};"
        : "+f"(d[0]), "+f"(d[1]), "+f"(d[2]), "+f"(d[3])
        : "r"(a[0]), "r"(a[1]), "r"(a[2]), "r"(a[3]), "r"(b0), "r"(b1));
}
__device__ __forceinline__ uint32_t pack_h2(float x, float y) {
    __half2 t = __floats2half2_rn(x, y);
    return *reinterpret_cast<uint32_t*>(&t);
}

#define RSTRIDE 144u        // padded 16-bit row stride in bytes (72 elems)

// ---------------------------------------------------------------------------
// Prep: W^T fp16 hi/lo (QSC folded into Q cols), bias. 256 CTAs x 4 k-cols.
// ---------------------------------------------------------------------------
__global__ __launch_bounds__(256) void prep_w(
    const float* __restrict__ WQ, const float* __restrict__ bQ,
    const float* __restrict__ WK, const float* __restrict__ bK,
    const float* __restrict__ WV, const float* __restrict__ bV)
{
    __shared__ float s[NOUT][5];
    const float QSC = 0.125f * 1.4426950408889634f;
    const int tid = threadIdx.x;
    const int k0  = blockIdx.x * 4;

    #pragma unroll
    for (int i = 0; i < 3; i++) {
        int idx = tid + i * 256;          // 0..767, n fast
        int k = idx / NOUT, n = idx - k * NOUT;
        float w;
        if (n < 64)       w = WQ[(size_t)(k0 + k) * DK + n] * QSC;
        else if (n < 128) w = WK[(size_t)(k0 + k) * DK + (n - 64)];
        else              w = WV[(size_t)(k0 + k) * DK + (n - 128)];
        s[n][k] = w;
    }
    __syncthreads();
    if (tid < NOUT) {
        __half hi[4], lo[4];
        #pragma unroll
        for (int k = 0; k < 4; k++) {
            float w = s[tid][k];
            hi[k] = __float2half_rn(w);
            lo[k] = __float2half_rn(w - __half2float(hi[k]));
        }
        *(uint2*)(g_WHh + (size_t)tid * DM + k0) = *(uint2*)hi;
        *(uint2*)(g_WHl + (size_t)tid * DM + k0) = *(uint2*)lo;
    }
    if (blockIdx.x == 0 && tid < NOUT) {
        float bb;
        if (tid < 64)       bb = bQ[tid] * QSC;
        else if (tid < 128) bb = bK[tid - 64];
        else                bb = bV[tid - 128];
        g_bias[tid] = bb;
    }
}

// ---------------------------------------------------------------------------
// Tensorized projection: grid (rows/128, 2). Each CTA: 128 rows x 96 n-cols.
// X fp16 single, W fp16 hi/lo (2 products). 92.5KB smem -> 2 CTAs/SM.
// ---------------------------------------------------------------------------
#define P_XB    0u            // X bufs: buf*18432 (128 rows)
#define P_WB    36864u        // W bufs: buf*27648 ; WH +0, WL +13824
#define P_BIAS  92160u        // 96 floats
#define P_TOTAL 92544u

__global__ __launch_bounds__(256, 2) void proj_tc(const float* __restrict__ X)
{
    extern __shared__ char smem[];
    const uint32_t sb = smem_to_u32(smem);
    const int tid  = threadIdx.x;
    const int wid  = tid >> 5;
    const int lane = tid & 31;
    const int gid  = lane >> 2;
    const int tq   = lane & 3;
    const int r0g  = blockIdx.x * 128;
    const int nbase = blockIdx.y * 96;

    float* biass = (float*)(smem + P_BIAS);
    if (tid < 96) biass[tid] = g_bias[nbase + tid];

    const int xrow  = tid >> 1;
    const int xhalf = tid & 1;
    const float* Xrow = X + (size_t)(r0g + xrow) * DM + xhalf * 32;
    const uint32_t xso = P_XB + (uint32_t)xrow * RSTRIDE + (uint32_t)xhalf * 64;

    // prologue: W chunk0 + X chunk0
    {
        #pragma unroll
        for (int t = 0; t < 6; t++) {
            int idx = tid + t * 256;          // 0..1535
            int arr = (idx >= 768);
            int i   = idx - arr * 768;
            int row = i >> 3, c = i & 7;
            const __half* src = (arr ? g_WHl : g_WHh) + (size_t)(nbase + row) * DM + c * 8;
            cpasync16(sb + P_WB + (uint32_t)arr * 13824u + (uint32_t)row * RSTRIDE + c * 16, src);
        }
        CP_COMMIT();
        float4 xr[8];
        #pragma unroll
        for (int i = 0; i < 8; i++) xr[i] = *(const float4*)(Xrow + 4 * i);
        #pragma unroll
        for (int i = 0; i < 8; i++) {
            uint2 v;
            v.x = pack_h2(xr[i].x, xr[i].y);
            v.y = pack_h2(xr[i].z, xr[i].w);
            *(uint2*)(smem + xso + 8 * i) = v;
        }
        CP_WAIT0();
        __syncthreads();
    }

    float O[12][4];
    #pragma unroll
    for (int n = 0; n < 12; n++)
        #pragma unroll
        for (int c = 0; c < 4; c++) O[n][c] = 0.f;

    const uint32_t aoff = (uint32_t)(wid * 16 + (lane & 15)) * RSTRIDE + (uint32_t)(lane >> 4) * 16;
    const uint32_t boff = (uint32_t)(((lane >> 4) & 1) * 8 + (lane & 7)) * RSTRIDE
                        + (uint32_t)((lane >> 3) & 1) * 16;

    for (int ch = 0; ch < 16; ch++) {
        const uint32_t XB = sb + P_XB + (uint32_t)(ch & 1) * 18432u;
        const uint32_t WB = sb + P_WB + (uint32_t)(ch & 1) * 27648u;
        const int nxt = ch + 1;
        float4 xr[8];

        if (nxt < 16) {
            const uint32_t WB1 = sb + P_WB + (uint32_t)(nxt & 1) * 27648u;
            #pragma unroll
            for (int t = 0; t < 6; t++) {
                int idx = tid + t * 256;
                int arr = (idx >= 768);
                int i   = idx - arr * 768;
                int row = i >> 3, c = i & 7;
                const __half* src = (arr ? g_WHl : g_WHh)
                                  + (size_t)(nbase + row) * DM + nxt * 64 + c * 8;
                cpasync16(WB1 + (uint32_t)arr * 13824u + (uint32_t)row * RSTRIDE + c * 16, src);
            }
            CP_COMMIT();
            #pragma unroll
            for (int i = 0; i < 8; i++) xr[i] = *(const float4*)(Xrow + nxt * 64 + 4 * i);
        }

        #pragma unroll
        for (int kc = 0; kc < 4; kc++) {
            uint32_t ah[4];
            ldsm_x4(ah, XB + aoff + kc * 32);
            #pragma unroll
            for (int p = 0; p < 6; p++) {
                uint32_t wh[4], wl[4];
                ldsm_x4(wh, WB + boff + (uint32_t)p * (16 * RSTRIDE) + kc * 32);
                mma_f16(O[2*p],   ah, wh[0], wh[1]);
                mma_f16(O[2*p+1], ah, wh[2], wh[3]);
                ldsm_x4(wl, WB + 13824u + boff + (uint32_t)p * (16 * RSTRIDE) + kc * 32);
                mma_f16(O[2*p],   ah, wl[0], wl[1]);
                mma_f16(O[2*p+1], ah, wl[2], wl[3]);
            }
        }

        if (nxt < 16) {
            const uint32_t xo = xso + (uint32_t)(nxt & 1) * 18432u;
            #pragma unroll
            for (int i = 0; i < 8; i++) {
                uint2 v;
                v.x = pack_h2(xr[i].x, xr[i].y);
                v.y = pack_h2(xr[i].z, xr[i].w);
                *(uint2*)(smem + xo + 8 * i) = v;
            }
            CP_WAIT0();
        }
        __syncthreads();
    }

    // ---- epilogue: +bias, emit fp16 flash operands
    const int rr0 = r0g + wid * 16 + gid;
    const int rr1 = rr0 + 8;
    #pragma unroll
    for (int nt = 0; nt < 12; nt++) {
        const int cl = nt * 8 + 2 * tq;
        const int cg = nbase + cl;
        const float b0 = biass[cl], b1 = biass[cl + 1];
        float v00 = O[nt][0] + b0, v01 = O[nt][1] + b1;
        float v10 = O[nt][2] + b0, v11 = O[nt][3] + b1;
        if (cg < 64) {
            *(__half2*)(g_Qf + (size_t)rr0 * DK + cg) = __floats2half2_rn(v00, v01);
            *(__half2*)(g_Qf + (size_t)rr1 * DK + cg) = __floats2half2_rn(v10, v11);
        } else if (cg < 128) {
            const int ck = cg - 64;
            *(__half2*)(g_Kf + (size_t)rr0 * DK + ck) = __floats2half2_rn(v00, v01);
            *(__half2*)(g_Kf + (size_t)rr1 * DK + ck) = __floats2half2_rn(v10, v11);
        } else {
            const int d0 = cg - 128, d1 = d0 + 1;
            g_Vt[(size_t)d0 * ROWS + rr0] = __float2half_rn(v00);
            g_Vt[(size_t)d1 * ROWS + rr0] = __float2half_rn(v01);
            g_Vt[(size_t)d0 * ROWS + rr1] = __float2half_rn(v10);
            g_Vt[(size_t)d1 * ROWS + rr1] = __float2half_rn(v11);
        }
    }
}

// ---------------------------------------------------------------------------
// Flash attention: round-6 body, split-KV (z dim), unnormalized partials.
// BM=128, 256 threads, 72KB smem -> 2 CTAs/SM.
// ---------------------------------------------------------------------------
#define SM_QF   0u
#define SM_BUF0 18432u
#define SM_BUFSZ 18432u      // K +0 (9216), V +9216
#define SM_TOTAL (SM_BUF0 + 3*SM_BUFSZ)

__device__ __forceinline__ void load_kv(uint32_t dst, int tid, size_t bSE, int j0)
{
    #pragma unroll
    for (int t = 0; t < 2; t++) {
        int i = tid + t * 256;            // K: 64 rows x 8 chunks
        int row = i >> 3, c = i & 7;
        cpasync16(dst + row * RSTRIDE + c * 16,
                  g_Kf + (bSE + j0 + row) * DK + c * 8);
    }
    #pragma unroll
    for (int t = 0; t < 2; t++) {
        int i = tid + t * 256;            // V: [d][key]
        int d = i >> 3, c = i & 7;
        cpasync16(dst + 9216u + d * RSTRIDE + c * 16,
                  g_Vt + (size_t)d * ROWS + bSE + j0 + c * 8);
    }
}

__global__ __launch_bounds__(256, 2) void flash_mma()
{
    extern __shared__ char smem[];
    const uint32_t sb = smem_to_u32(smem);
    const int tid  = threadIdx.x;
    const int wid  = tid >> 5;
    const int lane = tid & 31;
    const int gid  = lane >> 2;
    const int tq   = lane & 3;

    const int b  = blockIdx.y;
    const int q0 = blockIdx.x * BM;
    const int z  = blockIdx.z;
    const int k0base = z * NTZ * BN;
    const size_t bSE = (size_t)b * SEQ;

    // prologue: group0 = {Q, tile0}, group1 = {tile1}
    #pragma unroll
    for (int t = 0; t < 4; t++) {
        int idx = tid + t * 256;          // 128 rows x 8 chunks
        int row = idx >> 3, c = idx & 7;
        cpasync16(sb + SM_QF + row * RSTRIDE + c * 16,
                  g_Qf + (bSE + q0 + row) * DK + c * 8);
    }
    load_kv(sb + SM_BUF0, tid, bSE, k0base);
    CP_COMMIT();
    load_kv(sb + SM_BUF0 + SM_BUFSZ, tid, bSE, k0base + BN);
    CP_COMMIT();
    CP_WAIT1();
    __syncthreads();

    uint32_t qf[4][4];
    {
        uint32_t aoff = (uint32_t)(wid * 16 + (lane & 15)) * RSTRIDE + (uint32_t)(lane >> 4) * 16;
        #pragma unroll
        for (int kc = 0; kc < 4; kc++)
            ldsm_x4(qf[kc], sb + SM_QF + aoff + kc * 32);
    }

    float O[8][4];
    #pragma unroll
    for (int i = 0; i < 8; i++)
        #pragma unroll
        for (int c = 0; c < 4; c++) O[i][c] = 0.f;
    float lsum0 = 0.f, lsum1 = 0.f;

    const uint32_t boff = (uint32_t)(((lane >> 4) & 1) * 8 + (lane & 7)) * RSTRIDE
                        + (uint32_t)((lane >> 3) & 1) * 16;

    const uint32_t bufs[3] = {sb + SM_BUF0, sb + SM_BUF0 + SM_BUFSZ, sb + SM_BUF0 + 2*SM_BUFSZ};

    for (int j = 0; j < NTZ; j++) {
        const uint32_t buf = bufs[j % 3];

        // ---- S = Qf Kf^T (8 accumulators interleaved)
        float S[8][4];
        #pragma unroll
        for (int i = 0; i < 8; i++)
            #pragma unroll
            for (int c = 0; c < 4; c++) S[i][c] = 0.f;

        #pragma unroll
        for (int kc = 0; kc < 4; kc++) {
            #pragma unroll
            for (int nph = 0; nph < 2; nph++) {
                uint32_t r0[4], r1[4];
                ldsm_x4(r0, buf + boff + (uint32_t)(2*nph)   * (16 * RSTRIDE) + kc * 32);
                ldsm_x4(r1, buf + boff + (uint32_t)(2*nph+1) * (16 * RSTRIDE) + kc * 32);
                mma_f16(S[4*nph],   qf[kc], r0[0], r0[1]);
                mma_f16(S[4*nph+1], qf[kc], r0[2], r0[3]);
                mma_f16(S[4*nph+2], qf[kc], r1[0], r1[1]);
                mma_f16(S[4*nph+3], qf[kc], r1[2], r1[3]);
            }
        }

        // ---- softmax: p = exp2(s), quantize to fp16 A-fragments
        uint32_t Pf[4][4];
        #pragma unroll
        for (int kc2 = 0; kc2 < 4; kc2++) {
            const int nt0 = 2 * kc2, nt1 = nt0 + 1;
            float p00 = fast_exp2(S[nt0][0]), p01 = fast_exp2(S[nt0][1]);
            float p02 = fast_exp2(S[nt0][2]), p03 = fast_exp2(S[nt0][3]);
            float p10 = fast_exp2(S[nt1][0]), p11 = fast_exp2(S[nt1][1]);
            float p12 = fast_exp2(S[nt1][2]), p13 = fast_exp2(S[nt1][3]);
            lsum0 += p00 + p01 + p10 + p11;
            lsum1 += p02 + p03 + p12 + p13;
            Pf[kc2][0] = pack_h2(p00, p01);
            Pf[kc2][1] = pack_h2(p02, p03);
            Pf[kc2][2] = pack_h2(p10, p11);
            Pf[kc2][3] = pack_h2(p12, p13);
        }

        // ---- O += P Vt
        #pragma unroll
        for (int kc2 = 0; kc2 < 4; kc2++) {
            #pragma unroll
            for (int nph = 0; nph < 2; nph++) {
                uint32_t r0[4], r1[4];
                ldsm_x4(r0, buf + 9216u + boff + (uint32_t)(2*nph)   * (16 * RSTRIDE) + kc2 * 32);
                ldsm_x4(r1, buf + 9216u + boff + (uint32_t)(2*nph+1) * (16 * RSTRIDE) + kc2 * 32);
                mma_f16(O[4*nph],   Pf[kc2], r0[0], r0[1]);
                mma_f16(O[4*nph+1], Pf[kc2], r0[2], r0[3]);
                mma_f16(O[4*nph+2], Pf[kc2], r1[0], r1[1]);
                mma_f16(O[4*nph+3], Pf[kc2], r1[2], r1[3]);
            }
        }

        // ---- pipeline: prefetch j+2, ensure j+1 arrived, one barrier
        if (j + 2 < NTZ) {
            load_kv(bufs[(j + 2) % 3], tid, bSE, k0base + (j + 2) * BN);
            CP_COMMIT();
            CP_WAIT1();
        } else {
            CP_WAIT0();
        }
        __syncthreads();
    }

    // ---- epilogue: reduce row sums, write UNNORMALIZED partials
    lsum0 += __shfl_xor_sync(0xffffffffu, lsum0, 1);
    lsum0 += __shfl_xor_sync(0xffffffffu, lsum0, 2);
    lsum1 += __shfl_xor_sync(0xffffffffu, lsum1, 1);
    lsum1 += __shfl_xor_sync(0xffffffffu, lsum1, 2);

    const int row0 = q0 + wid * 16 + gid;
    float* o0 = g_Op + ((size_t)z * ROWS + bSE + row0) * DK;
    float* o1 = o0 + 8 * DK;
    if (tq == 0) {
        g_lp[(size_t)z * ROWS + bSE + row0]     = lsum0;
        g_lp[(size_t)z * ROWS + bSE + row0 + 8] = lsum1;
    }
    #pragma unroll
    for (int nt = 0; nt < 8; nt++) {
        const int col = nt * 8 + 2 * tq;
        *(float2*)(o0 + col) = make_float2(O[nt][0], O[nt][1]);
        *(float2*)(o1 + col) = make_float2(O[nt][2], O[nt][3]);
    }
}

// ---------------------------------------------------------------------------
// Combine: out = (O0 + O1) / (l0 + l1)
// ---------------------------------------------------------------------------
__global__ __launch_bounds__(256) void combine(float* __restrict__ out)
{
    const int idx = blockIdx.x * 256 + threadIdx.x;   // float4 index, 16/row
    const int row = idx >> 4;
    const float inv = 1.f / (g_lp[row] + g_lp[ROWS + row]);
    const float4 a = ((const float4*)g_Op)[idx];
    const float4 b = ((const float4*)g_Op)[idx + (ROWS * DK / 4)];
    float4 r;
    r.x = (a.x + b.x) * inv;
    r.y = (a.y + b.y) * inv;
    r.z = (a.z + b.z) * inv;
    r.w = (a.w + b.w) * inv;
    ((float4*)out)[idx] = r;
}

// ---------------------------------------------------------------------------
extern "C" void kernel_launch(void* const* d_in, const int* in_sizes, int n_in,
                              void* d_out, int out_size)
{
    const float* X  = (const float*)d_in[0];
    // d_in[1] cultural_embedding, d_in[8..10] WC,bC,lam: softmax-invariant -> unused
    const float* WQ = (const float*)d_in[2];
    const float* bQ = (const float*)d_in[3];
    const float* WK = (const float*)d_in[4];
    const float* bK = (const float*)d_in[5];
    const float* WV = (const float*)d_in[6];
    const float* bV = (const float*)d_in[7];
    float* out = (float*)d_out;

    cudaFuncSetAttribute(proj_tc,   cudaFuncAttributeMaxDynamicSharedMemorySize, P_TOTAL);
    cudaFuncSetAttribute(flash_mma, cudaFuncAttributeMaxDynamicSharedMemorySize, SM_TOTAL);

    prep_w<<<DM / 4, 256>>>(WQ, bQ, WK, bK, WV, bV);
    proj_tc<<<dim3(ROWS / 128, 2), 256, P_TOTAL>>>(X);
    flash_mma<<<dim3(SEQ / BM, BATCH, NZ), 256, SM_TOTAL>>>();
    combine<<<ROWS * DK / 4 / 256, 256>>>(out);
}

// round 9
// speedup vs baseline: 1.1711x; 1.0772x over previous
#include <cuda_runtime.h>
#include <cuda_fp16.h>
#include <cstdint>

#define BATCH 4
#define SEQ   4096
#define DM    1024
#define DK    64
#define ROWS  (BATCH*SEQ)
#define NOUT  192           // Q|K|V concat

#define BM 128              // queries per CTA (flash)
#define BN 64               // kv per tile
#define NT (SEQ/BN)         // 64 tiles total
#define NZ 2                // KV splits
#define NTZ (NT/NZ)         // 32 tiles per split

// ---------------------------------------------------------------------------
// Global scratch (fp16 operands; fp32 partials for split-KV combine).
// ---------------------------------------------------------------------------
__device__ __half g_Qf [ROWS*DK];
__device__ __half g_Kf [ROWS*DK];
__device__ __half g_Vt [DK*ROWS];      // transposed [d][row]
__device__ __half g_WHh[NOUT*DM];      // W^T [n][k], fp16 hi
__device__ __half g_WHl[NOUT*DM];      // fp16 lo (residual)
__device__ float  g_bias[NOUT];
__device__ float  g_Op[NZ*ROWS*DK];    // unnormalized O partials
__device__ float  g_lp[NZ*ROWS];       // row-sum partials

// ---------------------------------------------------------------------------
// Helpers (base-target PTX only)
// ---------------------------------------------------------------------------
__device__ __forceinline__ uint32_t smem_to_u32(const void* p) {
    uint32_t a;
    asm("{ .reg .u64 t; cvta.to.shared.u64 t, %1; cvt.u32.u64 %0, t; }" : "=r"(a) : "l"(p));
    return a;
}
__device__ __forceinline__ float fast_exp2(float x) {
    float y; asm("ex2.approx.ftz.f32 %0, %1;" : "=f"(y) : "f"(x)); return y;
}
__device__ __forceinline__ void cpasync16(uint32_t dst, const void* src) {
    asm volatile("cp.async.cg.shared.global [%0], [%1], 16;" :: "r"(dst), "l"(src));
}
#define CP_COMMIT() asm volatile("cp.async.commit_group;" ::: "memory")
#define CP_WAIT0()  asm volatile("cp.async.wait_group 0;" ::: "memory")
#define CP_WAIT1()  asm volatile("cp.async.wait_group 1;" ::: "memory")

__device__ __forceinline__ void ldsm_x4(uint32_t* r, uint32_t a) {
    asm volatile("ldmatrix.sync.aligned.m8n8.x4.shared.b16 {%0,%1,%2,%3}, [%4];"
        : "=r"(r[0]), "=r"(r[1]), "=r"(r[2]), "=r"(r[3]) : "r"(a));
}
__device__ __forceinline__ void mma_f16(float* d, const uint32_t* a,
                                        uint32_t b0, uint32_t b1) {
    asm volatile("mma.sync.aligned.m16n8k16.row.col.f32.f16.f16.f32 "
        "{%0,%1,%2,%3}, {%4,%5,%6,%7}, {%8,%9}, {%0,%1,%2,%3};"
        : "+f"(d[0]), "+f"(d[1]), "+f"(d[2]), "+f"(d[3])
        : "r"(a[0]), "r"(a[1]), "r"(a[2]), "r"(a[3]), "r"(b0), "r"(b1));
}
__device__ __forceinline__ uint32_t pack_h2(float x, float y) {
    __half2 t = __floats2half2_rn(x, y);
    return *reinterpret_cast<uint32_t*>(&t);
}

#define RSTRIDE 144u        // padded 16-bit row stride in bytes (72 elems)

// ---------------------------------------------------------------------------
// Prep: W^T fp16 hi/lo (QSC folded into Q cols), bias. 256 CTAs x 4 k-cols.
// ---------------------------------------------------------------------------
__global__ __launch_bounds__(256) void prep_w(
    const float* __restrict__ WQ, const float* __restrict__ bQ,
    const float* __restrict__ WK, const float* __restrict__ bK,
    const float* __restrict__ WV, const float* __restrict__ bV)
{
    __shared__ float s[NOUT][5];
    const float QSC = 0.125f * 1.4426950408889634f;
    const int tid = threadIdx.x;
    const int k0  = blockIdx.x * 4;

    #pragma unroll
    for (int i = 0; i < 3; i++) {
        int idx = tid + i * 256;          // 0..767, n fast
        int k = idx / NOUT, n = idx - k * NOUT;
        float w;
        if (n < 64)       w = WQ[(size_t)(k0 + k) * DK + n] * QSC;
        else if (n < 128) w = WK[(size_t)(k0 + k) * DK + (n - 64)];
        else              w = WV[(size_t)(k0 + k) * DK + (n - 128)];
        s[n][k] = w;
    }
    __syncthreads();
    if (tid < NOUT) {
        __half hi[4], lo[4];
        #pragma unroll
        for (int k = 0; k < 4; k++) {
            float w = s[tid][k];
            hi[k] = __float2half_rn(w);
            lo[k] = __float2half_rn(w - __half2float(hi[k]));
        }
        *(uint2*)(g_WHh + (size_t)tid * DM + k0) = *(uint2*)hi;
        *(uint2*)(g_WHl + (size_t)tid * DM + k0) = *(uint2*)lo;
    }
    if (blockIdx.x == 0 && tid < NOUT) {
        float bb;
        if (tid < 64)       bb = bQ[tid] * QSC;
        else if (tid < 128) bb = bK[tid - 64];
        else                bb = bV[tid - 128];
        g_bias[tid] = bb;
    }
}

// ---------------------------------------------------------------------------
// Tensorized projection: grid (rows/128, 2), 128 threads (4 warps x 32 rows).
// Each warp: M=32 (2 A-frags) x N=96. W B-fragments reused across both m-tiles.
// ---------------------------------------------------------------------------
#define P_XB    0u            // X bufs: buf*18432 (128 rows)
#define P_WB    36864u        // W bufs: buf*27648 ; WH +0, WL +13824
#define P_BIAS  92160u        // 96 floats
#define P_TOTAL 92544u

__global__ __launch_bounds__(128, 2) void proj_tc(const float* __restrict__ X)
{
    extern __shared__ char smem[];
    const uint32_t sb = smem_to_u32(smem);
    const int tid  = threadIdx.x;
    const int wid  = tid >> 5;
    const int lane = tid & 31;
    const int gid  = lane >> 2;
    const int tq   = lane & 3;
    const int r0g  = blockIdx.x * 128;
    const int nbase = blockIdx.y * 96;

    float* biass = (float*)(smem + P_BIAS);
    if (tid < 96) biass[tid] = g_bias[nbase + tid];

    const float* Xrow = X + (size_t)(r0g + tid) * DM;     // 1 thread per row
    const uint32_t xso = P_XB + (uint32_t)tid * RSTRIDE;

    // prologue: W chunk0 + X chunk0
    {
        #pragma unroll
        for (int t = 0; t < 12; t++) {
            int idx = tid + t * 128;          // 0..1535
            int arr = (idx >= 768);
            int i   = idx - arr * 768;
            int row = i >> 3, c = i & 7;
            const __half* src = (arr ? g_WHl : g_WHh) + (size_t)(nbase + row) * DM + c * 8;
            cpasync16(sb + P_WB + (uint32_t)arr * 13824u + (uint32_t)row * RSTRIDE + c * 16, src);
        }
        CP_COMMIT();
        float4 xr[16];
        #pragma unroll
        for (int i = 0; i < 16; i++) xr[i] = *(const float4*)(Xrow + 4 * i);
        #pragma unroll
        for (int i = 0; i < 16; i++) {
            uint2 v;
            v.x = pack_h2(xr[i].x, xr[i].y);
            v.y = pack_h2(xr[i].z, xr[i].w);
            *(uint2*)(smem + xso + 8 * i) = v;
        }
        CP_WAIT0();
        __syncthreads();
    }

    float O[2][12][4];
    #pragma unroll
    for (int m = 0; m < 2; m++)
        #pragma unroll
        for (int n = 0; n < 12; n++)
            #pragma unroll
            for (int c = 0; c < 4; c++) O[m][n][c] = 0.f;

    const uint32_t aoff0 = (uint32_t)(wid * 32 + (lane & 15)) * RSTRIDE + (uint32_t)(lane >> 4) * 16;
    const uint32_t aoff1 = aoff0 + 16 * RSTRIDE;
    const uint32_t boff = (uint32_t)(((lane >> 4) & 1) * 8 + (lane & 7)) * RSTRIDE
                        + (uint32_t)((lane >> 3) & 1) * 16;

    for (int ch = 0; ch < 16; ch++) {
        const uint32_t XB = sb + P_XB + (uint32_t)(ch & 1) * 18432u;
        const uint32_t WB = sb + P_WB + (uint32_t)(ch & 1) * 27648u;
        const int nxt = ch + 1;
        float4 xr[16];

        if (nxt < 16) {
            const uint32_t WB1 = sb + P_WB + (uint32_t)(nxt & 1) * 27648u;
            #pragma unroll
            for (int t = 0; t < 12; t++) {
                int idx = tid + t * 128;
                int arr = (idx >= 768);
                int i   = idx - arr * 768;
                int row = i >> 3, c = i & 7;
                const __half* src = (arr ? g_WHl : g_WHh)
                                  + (size_t)(nbase + row) * DM + nxt * 64 + c * 8;
                cpasync16(WB1 + (uint32_t)arr * 13824u + (uint32_t)row * RSTRIDE + c * 16, src);
            }
            CP_COMMIT();
            #pragma unroll
            for (int i = 0; i < 16; i++) xr[i] = *(const float4*)(Xrow + nxt * 64 + 4 * i);
        }

        #pragma unroll
        for (int kc = 0; kc < 4; kc++) {
            uint32_t a0[4], a1[4];
            ldsm_x4(a0, XB + aoff0 + kc * 32);
            ldsm_x4(a1, XB + aoff1 + kc * 32);
            #pragma unroll
            for (int p = 0; p < 6; p++) {
                uint32_t wh[4], wl[4];
                ldsm_x4(wh, WB + boff + (uint32_t)p * (16 * RSTRIDE) + kc * 32);
                mma_f16(O[0][2*p],   a0, wh[0], wh[1]);
                mma_f16(O[0][2*p+1], a0, wh[2], wh[3]);
                mma_f16(O[1][2*p],   a1, wh[0], wh[1]);
                mma_f16(O[1][2*p+1], a1, wh[2], wh[3]);
                ldsm_x4(wl, WB + 13824u + boff + (uint32_t)p * (16 * RSTRIDE) + kc * 32);
                mma_f16(O[0][2*p],   a0, wl[0], wl[1]);
                mma_f16(O[0][2*p+1], a0, wl[2], wl[3]);
                mma_f16(O[1][2*p],   a1, wl[0], wl[1]);
                mma_f16(O[1][2*p+1], a1, wl[2], wl[3]);
            }
        }

        if (nxt < 16) {
            const uint32_t xo = xso + (uint32_t)(nxt & 1) * 18432u;
            #pragma unroll
            for (int i = 0; i < 16; i++) {
                uint2 v;
                v.x = pack_h2(xr[i].x, xr[i].y);
                v.y = pack_h2(xr[i].z, xr[i].w);
                *(uint2*)(smem + xo + 8 * i) = v;
            }
            CP_WAIT0();
        }
        __syncthreads();
    }

    // ---- epilogue: +bias, emit fp16 flash operands
    #pragma unroll
    for (int m = 0; m < 2; m++) {
        const int rr0 = r0g + wid * 32 + m * 16 + gid;
        const int rr1 = rr0 + 8;
        #pragma unroll
        for (int nt = 0; nt < 12; nt++) {
            const int cl = nt * 8 + 2 * tq;
            const int cg = nbase + cl;
            const float b0 = biass[cl], b1 = biass[cl + 1];
            float v00 = O[m][nt][0] + b0, v01 = O[m][nt][1] + b1;
            float v10 = O[m][nt][2] + b0, v11 = O[m][nt][3] + b1;
            if (cg < 64) {
                *(__half2*)(g_Qf + (size_t)rr0 * DK + cg) = __floats2half2_rn(v00, v01);
                *(__half2*)(g_Qf + (size_t)rr1 * DK + cg) = __floats2half2_rn(v10, v11);
            } else if (cg < 128) {
                const int ck = cg - 64;
                *(__half2*)(g_Kf + (size_t)rr0 * DK + ck) = __floats2half2_rn(v00, v01);
                *(__half2*)(g_Kf + (size_t)rr1 * DK + ck) = __floats2half2_rn(v10, v11);
            } else {
                const int d0 = cg - 128, d1 = d0 + 1;
                g_Vt[(size_t)d0 * ROWS + rr0] = __float2half_rn(v00);
                g_Vt[(size_t)d1 * ROWS + rr0] = __float2half_rn(v01);
                g_Vt[(size_t)d0 * ROWS + rr1] = __float2half_rn(v10);
                g_Vt[(size_t)d1 * ROWS + rr1] = __float2half_rn(v11);
            }
        }
    }
}

// ---------------------------------------------------------------------------
// Flash attention: 128 threads (4 warps x 32 q rows), BM=128, split-KV.
// K/V B-fragments reused across both m-tiles -> half the ldsm traffic.
// ---------------------------------------------------------------------------
#define SM_QF   0u
#define SM_BUF0 18432u
#define SM_BUFSZ 18432u      // K +0 (9216), V +9216
#define SM_TOTAL (SM_BUF0 + 3*SM_BUFSZ)

__device__ __forceinline__ void load_kv(uint32_t dst, int tid, size_t bSE, int j0)
{
    #pragma unroll
    for (int t = 0; t < 4; t++) {
        int i = tid + t * 128;            // K: 64 rows x 8 chunks
        int row = i >> 3, c = i & 7;
        cpasync16(dst + row * RSTRIDE + c * 16,
                  g_Kf + (bSE + j0 + row) * DK + c * 8);
    }
    #pragma unroll
    for (int t = 0; t < 4; t++) {
        int i = tid + t * 128;            // V: [d][key]
        int d = i >> 3, c = i & 7;
        cpasync16(dst + 9216u + d * RSTRIDE + c * 16,
                  g_Vt + (size_t)d * ROWS + bSE + j0 + c * 8);
    }
}

__global__ __launch_bounds__(128, 2) void flash_mma()
{
    extern __shared__ char smem[];
    const uint32_t sb = smem_to_u32(smem);
    const int tid  = threadIdx.x;
    const int wid  = tid >> 5;
    const int lane = tid & 31;
    const int gid  = lane >> 2;
    const int tq   = lane & 3;

    const int b  = blockIdx.y;
    const int q0 = blockIdx.x * BM;
    const int z  = blockIdx.z;
    const int k0base = z * NTZ * BN;
    const size_t bSE = (size_t)b * SEQ;

    // prologue: group0 = {Q, tile0}, group1 = {tile1}
    #pragma unroll
    for (int t = 0; t < 8; t++) {
        int idx = tid + t * 128;          // 128 rows x 8 chunks
        int row = idx >> 3, c = idx & 7;
        cpasync16(sb + SM_QF + row * RSTRIDE + c * 16,
                  g_Qf + (bSE + q0 + row) * DK + c * 8);
    }
    load_kv(sb + SM_BUF0, tid, bSE, k0base);
    CP_COMMIT();
    load_kv(sb + SM_BUF0 + SM_BUFSZ, tid, bSE, k0base + BN);
    CP_COMMIT();
    CP_WAIT1();
    __syncthreads();

    // Q fragments: 2 m-tiles per warp (rows wid*32 .. wid*32+31)
    uint32_t qf[2][4][4];
    {
        const uint32_t a0 = (uint32_t)(wid * 32 + (lane & 15)) * RSTRIDE + (uint32_t)(lane >> 4) * 16;
        #pragma unroll
        for (int kc = 0; kc < 4; kc++) {
            ldsm_x4(qf[0][kc], sb + SM_QF + a0 + kc * 32);
            ldsm_x4(qf[1][kc], sb + SM_QF + a0 + 16 * RSTRIDE + kc * 32);
        }
    }

    float O[2][8][4];
    #pragma unroll
    for (int m = 0; m < 2; m++)
        #pragma unroll
        for (int i = 0; i < 8; i++)
            #pragma unroll
            for (int c = 0; c < 4; c++) O[m][i][c] = 0.f;
    float lsum[2][2] = {{0.f, 0.f}, {0.f, 0.f}};

    const uint32_t boff = (uint32_t)(((lane >> 4) & 1) * 8 + (lane & 7)) * RSTRIDE
                        + (uint32_t)((lane >> 3) & 1) * 16;

    const uint32_t bufs[3] = {sb + SM_BUF0, sb + SM_BUF0 + SM_BUFSZ, sb + SM_BUF0 + 2*SM_BUFSZ};

    for (int j = 0; j < NTZ; j++) {
        const uint32_t buf = bufs[j % 3];

        // ---- S = Qf Kf^T, both m-tiles share each K fragment
        float S[2][8][4];
        #pragma unroll
        for (int m = 0; m < 2; m++)
            #pragma unroll
            for (int i = 0; i < 8; i++)
                #pragma unroll
                for (int c = 0; c < 4; c++) S[m][i][c] = 0.f;

        #pragma unroll
        for (int kc = 0; kc < 4; kc++) {
            #pragma unroll
            for (int nph = 0; nph < 2; nph++) {
                uint32_t r0[4], r1[4];
                ldsm_x4(r0, buf + boff + (uint32_t)(2*nph)   * (16 * RSTRIDE) + kc * 32);
                ldsm_x4(r1, buf + boff + (uint32_t)(2*nph+1) * (16 * RSTRIDE) + kc * 32);
                #pragma unroll
                for (int m = 0; m < 2; m++) {
                    mma_f16(S[m][4*nph],   qf[m][kc], r0[0], r0[1]);
                    mma_f16(S[m][4*nph+1], qf[m][kc], r0[2], r0[3]);
                    mma_f16(S[m][4*nph+2], qf[m][kc], r1[0], r1[1]);
                    mma_f16(S[m][4*nph+3], qf[m][kc], r1[2], r1[3]);
                }
            }
        }

        // ---- softmax: p = exp2(s), quantize to fp16 A-fragments
        uint32_t Pf[2][4][4];
        #pragma unroll
        for (int m = 0; m < 2; m++) {
            #pragma unroll
            for (int kc2 = 0; kc2 < 4; kc2++) {
                const int nt0 = 2 * kc2, nt1 = nt0 + 1;
                float p00 = fast_exp2(S[m][nt0][0]), p01 = fast_exp2(S[m][nt0][1]);
                float p02 = fast_exp2(S[m][nt0][2]), p03 = fast_exp2(S[m][nt0][3]);
                float p10 = fast_exp2(S[m][nt1][0]), p11 = fast_exp2(S[m][nt1][1]);
                float p12 = fast_exp2(S[m][nt1][2]), p13 = fast_exp2(S[m][nt1][3]);
                lsum[m][0] += p00 + p01 + p10 + p11;
                lsum[m][1] += p02 + p03 + p12 + p13;
                Pf[m][kc2][0] = pack_h2(p00, p01);
                Pf[m][kc2][1] = pack_h2(p02, p03);
                Pf[m][kc2][2] = pack_h2(p10, p11);
                Pf[m][kc2][3] = pack_h2(p12, p13);
            }
        }

        // ---- O += P Vt, both m-tiles share each V fragment
        #pragma unroll
        for (int kc2 = 0; kc2 < 4; kc2++) {
            #pragma unroll
            for (int nph = 0; nph < 2; nph++) {
                uint32_t r0[4], r1[4];
                ldsm_x4(r0, buf + 9216u + boff + (uint32_t)(2*nph)   * (16 * RSTRIDE) + kc2 * 32);
                ldsm_x4(r1, buf + 9216u + boff + (uint32_t)(2*nph+1) * (16 * RSTRIDE) + kc2 * 32);
                #pragma unroll
                for (int m = 0; m < 2; m++) {
                    mma_f16(O[m][4*nph],   Pf[m][kc2], r0[0], r0[1]);
                    mma_f16(O[m][4*nph+1], Pf[m][kc2], r0[2], r0[3]);
                    mma_f16(O[m][4*nph+2], Pf[m][kc2], r1[0], r1[1]);
                    mma_f16(O[m][4*nph+3], Pf[m][kc2], r1[2], r1[3]);
                }
            }
        }

        // ---- pipeline: prefetch j+2, ensure j+1 arrived, one barrier
        if (j + 2 < NTZ) {
            load_kv(bufs[(j + 2) % 3], tid, bSE, k0base + (j + 2) * BN);
            CP_COMMIT();
            CP_WAIT1();
        } else {
            CP_WAIT0();
        }
        __syncthreads();
    }

    // ---- epilogue: reduce row sums, write unnormalized partials
    #pragma unroll
    for (int m = 0; m < 2; m++) {
        lsum[m][0] += __shfl_xor_sync(0xffffffffu, lsum[m][0], 1);
        lsum[m][0] += __shfl_xor_sync(0xffffffffu, lsum[m][0], 2);
        lsum[m][1] += __shfl_xor_sync(0xffffffffu, lsum[m][1], 1);
        lsum[m][1] += __shfl_xor_sync(0xffffffffu, lsum[m][1], 2);

        const int row0 = q0 + wid * 32 + m * 16 + gid;
        float* o0 = g_Op + ((size_t)z * ROWS + bSE + row0) * DK;
        float* o1 = o0 + 8 * DK;
        if (tq == 0) {
            g_lp[(size_t)z * ROWS + bSE + row0]     = lsum[m][0];
            g_lp[(size_t)z * ROWS + bSE + row0 + 8] = lsum[m][1];
        }
        #pragma unroll
        for (int nt = 0; nt < 8; nt++) {
            const int col = nt * 8 + 2 * tq;
            *(float2*)(o0 + col) = make_float2(O[m][nt][0], O[m][nt][1]);
            *(float2*)(o1 + col) = make_float2(O[m][nt][2], O[m][nt][3]);
        }
    }
}

// ---------------------------------------------------------------------------
// Combine: out = (O0 + O1) / (l0 + l1)
// ---------------------------------------------------------------------------
__global__ __launch_bounds__(256) void combine(float* __restrict__ out)
{
    const int idx = blockIdx.x * 256 + threadIdx.x;   // float4 index, 16/row
    const int row = idx >> 4;
    const float inv = 1.f / (g_lp[row] + g_lp[ROWS + row]);
    const float4 a = ((const float4*)g_Op)[idx];
    const float4 b = ((const float4*)g_Op)[idx + (ROWS * DK / 4)];
    float4 r;
    r.x = (a.x + b.x) * inv;
    r.y = (a.y + b.y) * inv;
    r.z = (a.z + b.z) * inv;
    r.w = (a.w + b.w) * inv;
    ((float4*)out)[idx] = r;
}

// ---------------------------------------------------------------------------
extern "C" void kernel_launch(void* const* d_in, const int* in_sizes, int n_in,
                              void* d_out, int out_size)
{
    const float* X  = (const float*)d_in[0];
    // d_in[1] cultural_embedding, d_in[8..10] WC,bC,lam: softmax-invariant -> unused
    const float* WQ = (const float*)d_in[2];
    const float* bQ = (const float*)d_in[3];
    const float* WK = (const float*)d_in[4];
    const float* bK = (const float*)d_in[5];
    const float* WV = (const float*)d_in[6];
    const float* bV = (const float*)d_in[7];
    float* out = (float*)d_out;

    cudaFuncSetAttribute(proj_tc,   cudaFuncAttributeMaxDynamicSharedMemorySize, P_TOTAL);
    cudaFuncSetAttribute(flash_mma, cudaFuncAttributeMaxDynamicSharedMemorySize, SM_TOTAL);

    prep_w<<<DM / 4, 256>>>(WQ, bQ, WK, bK, WV, bV);
    proj_tc<<<dim3(ROWS / 128, 2), 128, P_TOTAL>>>(X);
    flash_mma<<<dim3(SEQ / BM, BATCH, NZ), 128, SM_TOTAL>>>();
    combine<<<ROWS * DK / 4 / 256, 256>>>(out);
}

// round 10
// speedup vs baseline: 1.3435x; 1.1472x over previous
#include <cuda_runtime.h>
#include <cuda_fp16.h>
#include <cstdint>

#define BATCH 4
#define SEQ   4096
#define DM    1024
#define DK    64
#define ROWS  (BATCH*SEQ)
#define NOUT  192           // Q|K|V concat

#define BM 128              // queries per CTA (flash)
#define BN 64               // kv per tile
#define NT (SEQ/BN)         // 64 tiles total
#define NZ 2                // KV splits
#define NTZ (NT/NZ)         // 32 tiles per split

// ---------------------------------------------------------------------------
// Global scratch (fp16 operands; fp32 partials for split-KV combine).
// ---------------------------------------------------------------------------
__device__ __half g_Xf [ROWS*DM];      // X in fp16 (pre-converted)
__device__ __half g_Qf [ROWS*DK];
__device__ __half g_Kf [ROWS*DK];
__device__ __half g_Vt [DK*ROWS];      // transposed [d][row]
__device__ __half g_WHh[NOUT*DM];      // W^T [n][k], fp16 hi
__device__ __half g_WHl[NOUT*DM];      // fp16 lo (residual)
__device__ float  g_bias[NOUT];
__device__ float  g_Op[NZ*ROWS*DK];    // unnormalized O partials
__device__ float  g_lp[NZ*ROWS];       // row-sum partials

// ---------------------------------------------------------------------------
// Helpers (base-target PTX only)
// ---------------------------------------------------------------------------
__device__ __forceinline__ uint32_t smem_to_u32(const void* p) {
    uint32_t a;
    asm("{ .reg .u64 t; cvta.to.shared.u64 t, %1; cvt.u32.u64 %0, t; }" : "=r"(a) : "l"(p));
    return a;
}
__device__ __forceinline__ void cpasync16(uint32_t dst, const void* src) {
    asm volatile("cp.async.cg.shared.global [%0], [%1], 16;" :: "r"(dst), "l"(src));
}
#define CP_COMMIT() asm volatile("cp.async.commit_group;" ::: "memory")
#define CP_WAIT0()  asm volatile("cp.async.wait_group 0;" ::: "memory")
#define CP_WAIT1()  asm volatile("cp.async.wait_group 1;" ::: "memory")

__device__ __forceinline__ void ldsm_x4(uint32_t* r, uint32_t a) {
    asm volatile("ldmatrix.sync.aligned.m8n8.x4.shared.b16 {%0,%1,%2,%3}, [%4];"
        : "=r"(r[0]), "=r"(r[1]), "=r"(r[2]), "=r"(r[3]) : "r"(a));
}
__device__ __forceinline__ void mma_f16(float* d, const uint32_t* a,
                                        uint32_t b0, uint32_t b1) {
    asm volatile("mma.sync.aligned.m16n8k16.row.col.f32.f16.f16.f32 "
        "{%0,%1,%2,%3}, {%4,%5,%6,%7}, {%8,%9}, {%0,%1,%2,%3};"
        : "+f"(d[0]), "+f"(d[1]), "+f"(d[2]), "+f"(d[3])
        : "r"(a[0]), "r"(a[1]), "r"(a[2]), "r"(a[3]), "r"(b0), "r"(b1));
}
__device__ __forceinline__ uint32_t pack_h2(float x, float y) {
    __half2 t = __floats2half2_rn(x, y);
    return *reinterpret_cast<uint32_t*>(&t);
}
__device__ __forceinline__ uint32_t ex2_h2(uint32_t s) {
    uint32_t d;
    asm("ex2.approx.f16x2 %0, %1;" : "=r"(d) : "r"(s));
    return d;
}
__device__ __forceinline__ __half2 u2h2(uint32_t v) {
    return *reinterpret_cast<__half2*>(&v);
}

#define RSTRIDE 144u        // padded 16-bit row stride in bytes (72 elems)

// ---------------------------------------------------------------------------
// Prep (merged): blocks [0,256): W^T fp16 hi/lo + bias; blocks [256, 256+8192):
// X fp32 -> fp16 (coalesced, 8 floats/thread).
// ---------------------------------------------------------------------------
#define XCONV_BLKS (ROWS * DM / 8 / 256)   // 8192

__global__ __launch_bounds__(256) void prep_all(
    const float* __restrict__ X,
    const float* __restrict__ WQ, const float* __restrict__ bQ,
    const float* __restrict__ WK, const float* __restrict__ bK,
    const float* __restrict__ WV, const float* __restrict__ bV)
{
    const int tid = threadIdx.x;
    if (blockIdx.x >= 256) {
        // ---- X convert
        const int i = (blockIdx.x - 256) * 256 + tid;     // per 8 floats
        float4 a = ((const float4*)X)[2 * i];
        float4 b = ((const float4*)X)[2 * i + 1];
        uint4 v;
        v.x = pack_h2(a.x, a.y);
        v.y = pack_h2(a.z, a.w);
        v.z = pack_h2(b.x, b.y);
        v.w = pack_h2(b.z, b.w);
        ((uint4*)g_Xf)[i] = v;
        return;
    }
    // ---- W prep (256 blocks x 4 k-cols)
    __shared__ float s[NOUT][5];
    const float QSC = 0.125f * 1.4426950408889634f;
    const int k0 = blockIdx.x * 4;

    #pragma unroll
    for (int i = 0; i < 3; i++) {
        int idx = tid + i * 256;          // 0..767, n fast
        int k = idx / NOUT, n = idx - k * NOUT;
        float w;
        if (n < 64)       w = WQ[(size_t)(k0 + k) * DK + n] * QSC;
        else if (n < 128) w = WK[(size_t)(k0 + k) * DK + (n - 64)];
        else              w = WV[(size_t)(k0 + k) * DK + (n - 128)];
        s[n][k] = w;
    }
    __syncthreads();
    if (tid < NOUT) {
        __half hi[4], lo[4];
        #pragma unroll
        for (int k = 0; k < 4; k++) {
            float w = s[tid][k];
            hi[k] = __float2half_rn(w);
            lo[k] = __float2half_rn(w - __half2float(hi[k]));
        }
        *(uint2*)(g_WHh + (size_t)tid * DM + k0) = *(uint2*)hi;
        *(uint2*)(g_WHl + (size_t)tid * DM + k0) = *(uint2*)lo;
    }
    if (blockIdx.x == 0 && tid < NOUT) {
        float bb;
        if (tid < 64)       bb = bQ[tid] * QSC;
        else if (tid < 128) bb = bK[tid - 64];
        else                bb = bV[tid - 128];
        g_bias[tid] = bb;
    }
}

// ---------------------------------------------------------------------------
// Tensorized projection: grid (rows/128, 2), 128 threads (4 warps x 32 rows).
// X fp16 via cp.async (no fp32 path), W fp16 hi/lo (2 products).
// ---------------------------------------------------------------------------
#define P_XB    0u            // X bufs: buf*18432 (128 rows)
#define P_WB    36864u        // W bufs: buf*27648 ; WH +0, WL +13824
#define P_BIAS  92160u        // 96 floats
#define P_TOTAL 92544u

__device__ __forceinline__ void proj_load_chunk(uint32_t sb, int tid, int r0g,
                                                int nbase, int ch)
{
    const uint32_t XB = sb + P_XB + (uint32_t)(ch & 1) * 18432u;
    const uint32_t WB = sb + P_WB + (uint32_t)(ch & 1) * 27648u;
    #pragma unroll
    for (int t = 0; t < 8; t++) {         // X: 128 rows x 8 chunks of 16B
        int idx = tid + t * 128;
        int row = idx >> 3, c = idx & 7;
        cpasync16(XB + (uint32_t)row * RSTRIDE + c * 16,
                  g_Xf + (size_t)(r0g + row) * DM + ch * 64 + c * 8);
    }
    #pragma unroll
    for (int t = 0; t < 12; t++) {        // W hi/lo: 96 rows x 8 chunks x 2
        int idx = tid + t * 128;
        int arr = (idx >= 768);
        int i   = idx - arr * 768;
        int row = i >> 3, c = i & 7;
        const __half* src = (arr ? g_WHl : g_WHh)
                          + (size_t)(nbase + row) * DM + ch * 64 + c * 8;
        cpasync16(WB + (uint32_t)arr * 13824u + (uint32_t)row * RSTRIDE + c * 16, src);
    }
}

__global__ __launch_bounds__(128, 2) void proj_tc()
{
    extern __shared__ char smem[];
    const uint32_t sb = smem_to_u32(smem);
    const int tid  = threadIdx.x;
    const int wid  = tid >> 5;
    const int lane = tid & 31;
    const int gid  = lane >> 2;
    const int tq   = lane & 3;
    const int r0g  = blockIdx.x * 128;
    const int nbase = blockIdx.y * 96;

    float* biass = (float*)(smem + P_BIAS);
    if (tid < 96) biass[tid] = g_bias[nbase + tid];

    // prologue: chunk0
    proj_load_chunk(sb, tid, r0g, nbase, 0);
    CP_COMMIT();
    CP_WAIT0();
    __syncthreads();

    float O[2][12][4];
    #pragma unroll
    for (int m = 0; m < 2; m++)
        #pragma unroll
        for (int n = 0; n < 12; n++)
            #pragma unroll
            for (int c = 0; c < 4; c++) O[m][n][c] = 0.f;

    const uint32_t aoff0 = (uint32_t)(wid * 32 + (lane & 15)) * RSTRIDE + (uint32_t)(lane >> 4) * 16;
    const uint32_t aoff1 = aoff0 + 16 * RSTRIDE;
    const uint32_t boff = (uint32_t)(((lane >> 4) & 1) * 8 + (lane & 7)) * RSTRIDE
                        + (uint32_t)((lane >> 3) & 1) * 16;

    for (int ch = 0; ch < 16; ch++) {
        const uint32_t XB = sb + P_XB + (uint32_t)(ch & 1) * 18432u;
        const uint32_t WB = sb + P_WB + (uint32_t)(ch & 1) * 27648u;
        const int nxt = ch + 1;

        if (nxt < 16) {
            proj_load_chunk(sb, tid, r0g, nbase, nxt);
            CP_COMMIT();
        }

        #pragma unroll
        for (int kc = 0; kc < 4; kc++) {
            uint32_t a0[4], a1[4];
            ldsm_x4(a0, XB + aoff0 + kc * 32);
            ldsm_x4(a1, XB + aoff1 + kc * 32);
            #pragma unroll
            for (int p = 0; p < 6; p++) {
                uint32_t wh[4], wl[4];
                ldsm_x4(wh, WB + boff + (uint32_t)p * (16 * RSTRIDE) + kc * 32);
                mma_f16(O[0][2*p],   a0, wh[0], wh[1]);
                mma_f16(O[0][2*p+1], a0, wh[2], wh[3]);
                mma_f16(O[1][2*p],   a1, wh[0], wh[1]);
                mma_f16(O[1][2*p+1], a1, wh[2], wh[3]);
                ldsm_x4(wl, WB + 13824u + boff + (uint32_t)p * (16 * RSTRIDE) + kc * 32);
                mma_f16(O[0][2*p],   a0, wl[0], wl[1]);
                mma_f16(O[0][2*p+1], a0, wl[2], wl[3]);
                mma_f16(O[1][2*p],   a1, wl[0], wl[1]);
                mma_f16(O[1][2*p+1], a1, wl[2], wl[3]);
            }
        }

        if (nxt < 16) CP_WAIT0();
        __syncthreads();
    }

    // ---- epilogue: +bias, emit fp16 flash operands
    #pragma unroll
    for (int m = 0; m < 2; m++) {
        const int rr0 = r0g + wid * 32 + m * 16 + gid;
        const int rr1 = rr0 + 8;
        #pragma unroll
        for (int nt = 0; nt < 12; nt++) {
            const int cl = nt * 8 + 2 * tq;
            const int cg = nbase + cl;
            const float b0 = biass[cl], b1 = biass[cl + 1];
            float v00 = O[m][nt][0] + b0, v01 = O[m][nt][1] + b1;
            float v10 = O[m][nt][2] + b0, v11 = O[m][nt][3] + b1;
            if (cg < 64) {
                *(__half2*)(g_Qf + (size_t)rr0 * DK + cg) = __floats2half2_rn(v00, v01);
                *(__half2*)(g_Qf + (size_t)rr1 * DK + cg) = __floats2half2_rn(v10, v11);
            } else if (cg < 128) {
                const int ck = cg - 64;
                *(__half2*)(g_Kf + (size_t)rr0 * DK + ck) = __floats2half2_rn(v00, v01);
                *(__half2*)(g_Kf + (size_t)rr1 * DK + ck) = __floats2half2_rn(v10, v11);
            } else {
                const int d0 = cg - 128, d1 = d0 + 1;
                g_Vt[(size_t)d0 * ROWS + rr0] = __float2half_rn(v00);
                g_Vt[(size_t)d1 * ROWS + rr0] = __float2half_rn(v01);
                g_Vt[(size_t)d0 * ROWS + rr1] = __float2half_rn(v10);
                g_Vt[(size_t)d1 * ROWS + rr1] = __float2half_rn(v11);
            }
        }
    }
}

// ---------------------------------------------------------------------------
// Flash attention: 128 threads (4 warps x 32 q rows), BM=128, split-KV,
// fp16x2 exp (half the MUFU work), HADD2 row sums.
// ---------------------------------------------------------------------------
#define SM_QF   0u
#define SM_BUF0 18432u
#define SM_BUFSZ 18432u      // K +0 (9216), V +9216
#define SM_TOTAL (SM_BUF0 + 3*SM_BUFSZ)

__device__ __forceinline__ void load_kv(uint32_t dst, int tid, size_t bSE, int j0)
{
    #pragma unroll
    for (int t = 0; t < 4; t++) {
        int i = tid + t * 128;            // K: 64 rows x 8 chunks
        int row = i >> 3, c = i & 7;
        cpasync16(dst + row * RSTRIDE + c * 16,
                  g_Kf + (bSE + j0 + row) * DK + c * 8);
    }
    #pragma unroll
    for (int t = 0; t < 4; t++) {
        int i = tid + t * 128;            // V: [d][key]
        int d = i >> 3, c = i & 7;
        cpasync16(dst + 9216u + d * RSTRIDE + c * 16,
                  g_Vt + (size_t)d * ROWS + bSE + j0 + c * 8);
    }
}

__global__ __launch_bounds__(128, 2) void flash_mma()
{
    extern __shared__ char smem[];
    const uint32_t sb = smem_to_u32(smem);
    const int tid  = threadIdx.x;
    const int wid  = tid >> 5;
    const int lane = tid & 31;
    const int gid  = lane >> 2;
    const int tq   = lane & 3;

    const int b  = blockIdx.y;
    const int q0 = blockIdx.x * BM;
    const int z  = blockIdx.z;
    const int k0base = z * NTZ * BN;
    const size_t bSE = (size_t)b * SEQ;

    // prologue: group0 = {Q, tile0}, group1 = {tile1}
    #pragma unroll
    for (int t = 0; t < 8; t++) {
        int idx = tid + t * 128;          // 128 rows x 8 chunks
        int row = idx >> 3, c = idx & 7;
        cpasync16(sb + SM_QF + row * RSTRIDE + c * 16,
                  g_Qf + (bSE + q0 + row) * DK + c * 8);
    }
    load_kv(sb + SM_BUF0, tid, bSE, k0base);
    CP_COMMIT();
    load_kv(sb + SM_BUF0 + SM_BUFSZ, tid, bSE, k0base + BN);
    CP_COMMIT();
    CP_WAIT1();
    __syncthreads();

    // Q fragments: 2 m-tiles per warp (rows wid*32 .. wid*32+31)
    uint32_t qf[2][4][4];
    {
        const uint32_t a0 = (uint32_t)(wid * 32 + (lane & 15)) * RSTRIDE + (uint32_t)(lane >> 4) * 16;
        #pragma unroll
        for (int kc = 0; kc < 4; kc++) {
            ldsm_x4(qf[0][kc], sb + SM_QF + a0 + kc * 32);
            ldsm_x4(qf[1][kc], sb + SM_QF + a0 + 16 * RSTRIDE + kc * 32);
        }
    }

    float O[2][8][4];
    #pragma unroll
    for (int m = 0; m < 2; m++)
        #pragma unroll
        for (int i = 0; i < 8; i++)
            #pragma unroll
            for (int c = 0; c < 4; c++) O[m][i][c] = 0.f;
    float lsum[2][2] = {{0.f, 0.f}, {0.f, 0.f}};

    const uint32_t boff = (uint32_t)(((lane >> 4) & 1) * 8 + (lane & 7)) * RSTRIDE
                        + (uint32_t)((lane >> 3) & 1) * 16;

    const uint32_t bufs[3] = {sb + SM_BUF0, sb + SM_BUF0 + SM_BUFSZ, sb + SM_BUF0 + 2*SM_BUFSZ};

    for (int j = 0; j < NTZ; j++) {
        const uint32_t buf = bufs[j % 3];

        // ---- S = Qf Kf^T, both m-tiles share each K fragment
        float S[2][8][4];
        #pragma unroll
        for (int m = 0; m < 2; m++)
            #pragma unroll
            for (int i = 0; i < 8; i++)
                #pragma unroll
                for (int c = 0; c < 4; c++) S[m][i][c] = 0.f;

        #pragma unroll
        for (int kc = 0; kc < 4; kc++) {
            #pragma unroll
            for (int nph = 0; nph < 2; nph++) {
                uint32_t r0[4], r1[4];
                ldsm_x4(r0, buf + boff + (uint32_t)(2*nph)   * (16 * RSTRIDE) + kc * 32);
                ldsm_x4(r1, buf + boff + (uint32_t)(2*nph+1) * (16 * RSTRIDE) + kc * 32);
                #pragma unroll
                for (int m = 0; m < 2; m++) {
                    mma_f16(S[m][4*nph],   qf[m][kc], r0[0], r0[1]);
                    mma_f16(S[m][4*nph+1], qf[m][kc], r0[2], r0[3]);
                    mma_f16(S[m][4*nph+2], qf[m][kc], r1[0], r1[1]);
                    mma_f16(S[m][4*nph+3], qf[m][kc], r1[2], r1[3]);
                }
            }
        }

        // ---- softmax: pack s to fp16x2, p = ex2.f16x2 (half the MUFU work)
        uint32_t Pf[2][4][4];
        #pragma unroll
        for (int m = 0; m < 2; m++) {
            __half2 a0 = __floats2half2_rn(0.f, 0.f);
            __half2 a1 = a0;
            #pragma unroll
            for (int kc2 = 0; kc2 < 4; kc2++) {
                const int nt0 = 2 * kc2, nt1 = nt0 + 1;
                Pf[m][kc2][0] = ex2_h2(pack_h2(S[m][nt0][0], S[m][nt0][1]));
                Pf[m][kc2][1] = ex2_h2(pack_h2(S[m][nt0][2], S[m][nt0][3]));
                Pf[m][kc2][2] = ex2_h2(pack_h2(S[m][nt1][0], S[m][nt1][1]));
                Pf[m][kc2][3] = ex2_h2(pack_h2(S[m][nt1][2], S[m][nt1][3]));
                a0 = __hadd2(a0, __hadd2(u2h2(Pf[m][kc2][0]), u2h2(Pf[m][kc2][2])));
                a1 = __hadd2(a1, __hadd2(u2h2(Pf[m][kc2][1]), u2h2(Pf[m][kc2][3])));
            }
            lsum[m][0] += __low2float(a0) + __high2float(a0);
            lsum[m][1] += __low2float(a1) + __high2float(a1);
        }

        // ---- O += P Vt, both m-tiles share each V fragment
        #pragma unroll
        for (int kc2 = 0; kc2 < 4; kc2++) {
            #pragma unroll
            for (int nph = 0; nph < 2; nph++) {
                uint32_t r0[4], r1[4];
                ldsm_x4(r0, buf + 9216u + boff + (uint32_t)(2*nph)   * (16 * RSTRIDE) + kc2 * 32);
                ldsm_x4(r1, buf + 9216u + boff + (uint32_t)(2*nph+1) * (16 * RSTRIDE) + kc2 * 32);
                #pragma unroll
                for (int m = 0; m < 2; m++) {
                    mma_f16(O[m][4*nph],   Pf[m][kc2], r0[0], r0[1]);
                    mma_f16(O[m][4*nph+1], Pf[m][kc2], r0[2], r0[3]);
                    mma_f16(O[m][4*nph+2], Pf[m][kc2], r1[0], r1[1]);
                    mma_f16(O[m][4*nph+3], Pf[m][kc2], r1[2], r1[3]);
                }
            }
        }

        // ---- pipeline: prefetch j+2, ensure j+1 arrived, one barrier
        if (j + 2 < NTZ) {
            load_kv(bufs[(j + 2) % 3], tid, bSE, k0base + (j + 2) * BN);
            CP_COMMIT();
            CP_WAIT1();
        } else {
            CP_WAIT0();
        }
        __syncthreads();
    }

    // ---- epilogue: reduce row sums, write unnormalized partials
    #pragma unroll
    for (int m = 0; m < 2; m++) {
        lsum[m][0] += __shfl_xor_sync(0xffffffffu, lsum[m][0], 1);
        lsum[m][0] += __shfl_xor_sync(0xffffffffu, lsum[m][0], 2);
        lsum[m][1] += __shfl_xor_sync(0xffffffffu, lsum[m][1], 1);
        lsum[m][1] += __shfl_xor_sync(0xffffffffu, lsum[m][1], 2);

        const int row0 = q0 + wid * 32 + m * 16 + gid;
        float* o0 = g_Op + ((size_t)z * ROWS + bSE + row0) * DK;
        float* o1 = o0 + 8 * DK;
        if (tq == 0) {
            g_lp[(size_t)z * ROWS + bSE + row0]     = lsum[m][0];
            g_lp[(size_t)z * ROWS + bSE + row0 + 8] = lsum[m][1];
        }
        #pragma unroll
        for (int nt = 0; nt < 8; nt++) {
            const int col = nt * 8 + 2 * tq;
            *(float2*)(o0 + col) = make_float2(O[m][nt][0], O[m][nt][1]);
            *(float2*)(o1 + col) = make_float2(O[m][nt][2], O[m][nt][3]);
        }
    }
}

// ---------------------------------------------------------------------------
// Combine: out = (O0 + O1) / (l0 + l1), 2 elements per thread for ILP.
// ---------------------------------------------------------------------------
#define CMB_HALF (ROWS * DK / 4 / 2)

__global__ __launch_bounds__(256) void combine(float* __restrict__ out)
{
    const int i0 = blockIdx.x * 256 + threadIdx.x;   // float4 index
    const int i1 = i0 + CMB_HALF;
    const int r0 = i0 >> 4, r1 = i1 >> 4;
    const float inv0 = 1.f / (g_lp[r0] + g_lp[ROWS + r0]);
    const float inv1 = 1.f / (g_lp[r1] + g_lp[ROWS + r1]);
    const float4 a0 = ((const float4*)g_Op)[i0];
    const float4 b0 = ((const float4*)g_Op)[i0 + (ROWS * DK / 4)];
    const float4 a1 = ((const float4*)g_Op)[i1];
    const float4 b1 = ((const float4*)g_Op)[i1 + (ROWS * DK / 4)];
    float4 r;
    r.x = (a0.x + b0.x) * inv0; r.y = (a0.y + b0.y) * inv0;
    r.z = (a0.z + b0.z) * inv0; r.w = (a0.w + b0.w) * inv0;
    ((float4*)out)[i0] = r;
    r.x = (a1.x + b1.x) * inv1; r.y = (a1.y + b1.y) * inv1;
    r.z = (a1.z + b1.z) * inv1; r.w = (a1.w + b1.w) * inv1;
    ((float4*)out)[i1] = r;
}

// ---------------------------------------------------------------------------
extern "C" void kernel_launch(void* const* d_in, const int* in_sizes, int n_in,
                              void* d_out, int out_size)
{
    const float* X  = (const float*)d_in[0];
    // d_in[1] cultural_embedding, d_in[8..10] WC,bC,lam: softmax-invariant -> unused
    const float* WQ = (const float*)d_in[2];
    const float* bQ = (const float*)d_in[3];
    const float* WK = (const float*)d_in[4];
    const float* bK = (const float*)d_in[5];
    const float* WV = (const float*)d_in[6];
    const float* bV = (const float*)d_in[7];
    float* out = (float*)d_out;

    cudaFuncSetAttribute(proj_tc,   cudaFuncAttributeMaxDynamicSharedMemorySize, P_TOTAL);
    cudaFuncSetAttribute(flash_mma, cudaFuncAttributeMaxDynamicSharedMemorySize, SM_TOTAL);

    prep_all<<<256 + XCONV_BLKS, 256>>>(X, WQ, bQ, WK, bK, WV, bV);
    proj_tc<<<dim3(ROWS / 128, 2), 128, P_TOTAL>>>();
    flash_mma<<<dim3(SEQ / BM, BATCH, NZ), 128, SM_TOTAL>>>();
    combine<<<CMB_HALF / 256, 256>>>(out);
}

// round 11
// speedup vs baseline: 1.6040x; 1.1939x over previous
#include <cuda_runtime.h>
#include <cuda_fp16.h>
#include <cstdint>

#define BATCH 4
#define SEQ   4096
#define DM    1024
#define DK    64
#define ROWS  (BATCH*SEQ)
#define NOUT  192           // Q|K|V concat

#define BM 128              // queries per CTA (flash)
#define BN 64               // kv per tile
#define NT (SEQ/BN)         // 64 tiles total
#define NZ 2                // KV splits
#define NTZ (NT/NZ)         // 32 tiles per split

// ---------------------------------------------------------------------------
// Global scratch (fp16 operands; fp32 partials for split-KV combine).
// ---------------------------------------------------------------------------
__device__ __half g_Xf [ROWS*DM];      // X in fp16 (pre-converted)
__device__ __half g_Qf [ROWS*DK];
__device__ __half g_Kf [ROWS*DK];
__device__ __half g_Vt [DK*ROWS];      // transposed [d][row]
__device__ __half g_WT [NOUT*DM];      // W^T [n][k], fp16
__device__ float  g_bias[NOUT];
__device__ float  g_Op[NZ*ROWS*DK];    // unnormalized O partials
__device__ float  g_lp[NZ*ROWS];       // row-sum partials

// ---------------------------------------------------------------------------
// Helpers (base-target PTX only)
// ---------------------------------------------------------------------------
__device__ __forceinline__ uint32_t smem_to_u32(const void* p) {
    uint32_t a;
    asm("{ .reg .u64 t; cvta.to.shared.u64 t, %1; cvt.u32.u64 %0, t; }" : "=r"(a) : "l"(p));
    return a;
}
__device__ __forceinline__ void cpasync16(uint32_t dst, const void* src) {
    asm volatile("cp.async.cg.shared.global [%0], [%1], 16;" :: "r"(dst), "l"(src));
}
#define CP_COMMIT() asm volatile("cp.async.commit_group;" ::: "memory")
#define CP_WAIT0()  asm volatile("cp.async.wait_group 0;" ::: "memory")
#define CP_WAIT1()  asm volatile("cp.async.wait_group 1;" ::: "memory")

__device__ __forceinline__ void ldsm_x4(uint32_t* r, uint32_t a) {
    asm volatile("ldmatrix.sync.aligned.m8n8.x4.shared.b16 {%0,%1,%2,%3}, [%4];"
        : "=r"(r[0]), "=r"(r[1]), "=r"(r[2]), "=r"(r[3]) : "r"(a));
}
__device__ __forceinline__ void mma_f16(float* d, const uint32_t* a,
                                        uint32_t b0, uint32_t b1) {
    asm volatile("mma.sync.aligned.m16n8k16.row.col.f32.f16.f16.f32 "
        "{%0,%1,%2,%3}, {%4,%5,%6,%7}, {%8,%9}, {%0,%1,%2,%3};"
        : "+f"(d[0]), "+f"(d[1]), "+f"(d[2]), "+f"(d[3])
        : "r"(a[0]), "r"(a[1]), "r"(a[2]), "r"(a[3]), "r"(b0), "r"(b1));
}
__device__ __forceinline__ uint32_t pack_h2(float x, float y) {
    __half2 t = __floats2half2_rn(x, y);
    return *reinterpret_cast<uint32_t*>(&t);
}
__device__ __forceinline__ uint32_t ex2_h2(uint32_t s) {
    uint32_t d;
    asm("ex2.approx.f16x2 %0, %1;" : "=r"(d) : "r"(s));
    return d;
}
__device__ __forceinline__ __half2 u2h2(uint32_t v) {
    return *reinterpret_cast<__half2*>(&v);
}

#define RSTRIDE 144u        // padded 16-bit row stride in bytes (72 elems)

// ---------------------------------------------------------------------------
// Prep (merged): blocks [0,256): W^T fp16 + bias; blocks [256, 256+8192):
// X fp32 -> fp16 (coalesced, 8 floats/thread).
// ---------------------------------------------------------------------------
#define XCONV_BLKS (ROWS * DM / 8 / 256)   // 8192

__global__ __launch_bounds__(256) void prep_all(
    const float* __restrict__ X,
    const float* __restrict__ WQ, const float* __restrict__ bQ,
    const float* __restrict__ WK, const float* __restrict__ bK,
    const float* __restrict__ WV, const float* __restrict__ bV)
{
    const int tid = threadIdx.x;
    if (blockIdx.x >= 256) {
        // ---- X convert
        const int i = (blockIdx.x - 256) * 256 + tid;     // per 8 floats
        float4 a = ((const float4*)X)[2 * i];
        float4 b = ((const float4*)X)[2 * i + 1];
        uint4 v;
        v.x = pack_h2(a.x, a.y);
        v.y = pack_h2(a.z, a.w);
        v.z = pack_h2(b.x, b.y);
        v.w = pack_h2(b.z, b.w);
        ((uint4*)g_Xf)[i] = v;
        return;
    }
    // ---- W prep (256 blocks x 4 k-cols)
    __shared__ float s[NOUT][5];
    const float QSC = 0.125f * 1.4426950408889634f;
    const int k0 = blockIdx.x * 4;

    #pragma unroll
    for (int i = 0; i < 3; i++) {
        int idx = tid + i * 256;          // 0..767, n fast
        int k = idx / NOUT, n = idx - k * NOUT;
        float w;
        if (n < 64)       w = WQ[(size_t)(k0 + k) * DK + n] * QSC;
        else if (n < 128) w = WK[(size_t)(k0 + k) * DK + (n - 64)];
        else              w = WV[(size_t)(k0 + k) * DK + (n - 128)];
        s[n][k] = w;
    }
    __syncthreads();
    if (tid < NOUT) {
        __half hv[4];
        #pragma unroll
        for (int k = 0; k < 4; k++) hv[k] = __float2half_rn(s[tid][k]);
        *(uint2*)(g_WT + (size_t)tid * DM + k0) = *(uint2*)hv;
    }
    if (blockIdx.x == 0 && tid < NOUT) {
        float bb;
        if (tid < 64)       bb = bQ[tid] * QSC;
        else if (tid < 128) bb = bK[tid - 64];
        else                bb = bV[tid - 128];
        g_bias[tid] = bb;
    }
}

// ---------------------------------------------------------------------------
// Tensorized projection: grid (rows/128, 2), 128 threads (4 warps x 32 rows).
// X fp16, W fp16 single (1 product). 63KB smem -> 3 CTAs/SM.
// ---------------------------------------------------------------------------
#define P_XB    0u            // X bufs: buf*18432 (128 rows)
#define P_WB    36864u        // W bufs: buf*13824 (96 rows)
#define P_BIAS  64512u        // 96 floats
#define P_TOTAL 64896u

__device__ __forceinline__ void proj_load_chunk(uint32_t sb, int tid, int r0g,
                                                int nbase, int ch)
{
    const uint32_t XB = sb + P_XB + (uint32_t)(ch & 1) * 18432u;
    const uint32_t WB = sb + P_WB + (uint32_t)(ch & 1) * 13824u;
    #pragma unroll
    for (int t = 0; t < 8; t++) {         // X: 128 rows x 8 chunks of 16B
        int idx = tid + t * 128;
        int row = idx >> 3, c = idx & 7;
        cpasync16(XB + (uint32_t)row * RSTRIDE + c * 16,
                  g_Xf + (size_t)(r0g + row) * DM + ch * 64 + c * 8);
    }
    #pragma unroll
    for (int t = 0; t < 6; t++) {         // W: 96 rows x 8 chunks
        int idx = tid + t * 128;
        int row = idx >> 3, c = idx & 7;
        cpasync16(WB + (uint32_t)row * RSTRIDE + c * 16,
                  g_WT + (size_t)(nbase + row) * DM + ch * 64 + c * 8);
    }
}

__global__ __launch_bounds__(128, 3) void proj_tc()
{
    extern __shared__ char smem[];
    const uint32_t sb = smem_to_u32(smem);
    const int tid  = threadIdx.x;
    const int wid  = tid >> 5;
    const int lane = tid & 31;
    const int gid  = lane >> 2;
    const int tq   = lane & 3;
    const int r0g  = blockIdx.x * 128;
    const int nbase = blockIdx.y * 96;

    float* biass = (float*)(smem + P_BIAS);
    if (tid < 96) biass[tid] = g_bias[nbase + tid];

    // prologue: chunk0
    proj_load_chunk(sb, tid, r0g, nbase, 0);
    CP_COMMIT();
    CP_WAIT0();
    __syncthreads();

    float O[2][12][4];
    #pragma unroll
    for (int m = 0; m < 2; m++)
        #pragma unroll
        for (int n = 0; n < 12; n++)
            #pragma unroll
            for (int c = 0; c < 4; c++) O[m][n][c] = 0.f;

    const uint32_t aoff0 = (uint32_t)(wid * 32 + (lane & 15)) * RSTRIDE + (uint32_t)(lane >> 4) * 16;
    const uint32_t aoff1 = aoff0 + 16 * RSTRIDE;
    const uint32_t boff = (uint32_t)(((lane >> 4) & 1) * 8 + (lane & 7)) * RSTRIDE
                        + (uint32_t)((lane >> 3) & 1) * 16;

    for (int ch = 0; ch < 16; ch++) {
        const uint32_t XB = sb + P_XB + (uint32_t)(ch & 1) * 18432u;
        const uint32_t WB = sb + P_WB + (uint32_t)(ch & 1) * 13824u;
        const int nxt = ch + 1;

        if (nxt < 16) {
            proj_load_chunk(sb, tid, r0g, nbase, nxt);
            CP_COMMIT();
        }

        #pragma unroll
        for (int kc = 0; kc < 4; kc++) {
            uint32_t a0[4], a1[4];
            ldsm_x4(a0, XB + aoff0 + kc * 32);
            ldsm_x4(a1, XB + aoff1 + kc * 32);
            #pragma unroll
            for (int p = 0; p < 6; p++) {
                uint32_t wh[4];
                ldsm_x4(wh, WB + boff + (uint32_t)p * (16 * RSTRIDE) + kc * 32);
                mma_f16(O[0][2*p],   a0, wh[0], wh[1]);
                mma_f16(O[0][2*p+1], a0, wh[2], wh[3]);
                mma_f16(O[1][2*p],   a1, wh[0], wh[1]);
                mma_f16(O[1][2*p+1], a1, wh[2], wh[3]);
            }
        }

        if (nxt < 16) CP_WAIT0();
        __syncthreads();
    }

    // ---- epilogue: +bias, emit fp16 flash operands
    #pragma unroll
    for (int m = 0; m < 2; m++) {
        const int rr0 = r0g + wid * 32 + m * 16 + gid;
        const int rr1 = rr0 + 8;
        #pragma unroll
        for (int nt = 0; nt < 12; nt++) {
            const int cl = nt * 8 + 2 * tq;
            const int cg = nbase + cl;
            const float b0 = biass[cl], b1 = biass[cl + 1];
            float v00 = O[m][nt][0] + b0, v01 = O[m][nt][1] + b1;
            float v10 = O[m][nt][2] + b0, v11 = O[m][nt][3] + b1;
            if (cg < 64) {
                *(__half2*)(g_Qf + (size_t)rr0 * DK + cg) = __floats2half2_rn(v00, v01);
                *(__half2*)(g_Qf + (size_t)rr1 * DK + cg) = __floats2half2_rn(v10, v11);
            } else if (cg < 128) {
                const int ck = cg - 64;
                *(__half2*)(g_Kf + (size_t)rr0 * DK + ck) = __floats2half2_rn(v00, v01);
                *(__half2*)(g_Kf + (size_t)rr1 * DK + ck) = __floats2half2_rn(v10, v11);
            } else {
                const int d0 = cg - 128, d1 = d0 + 1;
                g_Vt[(size_t)d0 * ROWS + rr0] = __float2half_rn(v00);
                g_Vt[(size_t)d1 * ROWS + rr0] = __float2half_rn(v01);
                g_Vt[(size_t)d0 * ROWS + rr1] = __float2half_rn(v10);
                g_Vt[(size_t)d1 * ROWS + rr1] = __float2half_rn(v11);
            }
        }
    }
}

// ---------------------------------------------------------------------------
// Flash attention: 128 threads (4 warps x 32 q rows), BM=128, split-KV,
// fp16x2 exp, HADD2 row sums. (Verified round-10 body, unchanged.)
// ---------------------------------------------------------------------------
#define SM_QF   0u
#define SM_BUF0 18432u
#define SM_BUFSZ 18432u      // K +0 (9216), V +9216
#define SM_TOTAL (SM_BUF0 + 3*SM_BUFSZ)

__device__ __forceinline__ void load_kv(uint32_t dst, int tid, size_t bSE, int j0)
{
    #pragma unroll
    for (int t = 0; t < 4; t++) {
        int i = tid + t * 128;            // K: 64 rows x 8 chunks
        int row = i >> 3, c = i & 7;
        cpasync16(dst + row * RSTRIDE + c * 16,
                  g_Kf + (bSE + j0 + row) * DK + c * 8);
    }
    #pragma unroll
    for (int t = 0; t < 4; t++) {
        int i = tid + t * 128;            // V: [d][key]
        int d = i >> 3, c = i & 7;
        cpasync16(dst + 9216u + d * RSTRIDE + c * 16,
                  g_Vt + (size_t)d * ROWS + bSE + j0 + c * 8);
    }
}

__global__ __launch_bounds__(128, 2) void flash_mma()
{
    extern __shared__ char smem[];
    const uint32_t sb = smem_to_u32(smem);
    const int tid  = threadIdx.x;
    const int wid  = tid >> 5;
    const int lane = tid & 31;
    const int gid  = lane >> 2;
    const int tq   = lane & 3;

    const int b  = blockIdx.y;
    const int q0 = blockIdx.x * BM;
    const int z  = blockIdx.z;
    const int k0base = z * NTZ * BN;
    const size_t bSE = (size_t)b * SEQ;

    // prologue: group0 = {Q, tile0}, group1 = {tile1}
    #pragma unroll
    for (int t = 0; t < 8; t++) {
        int idx = tid + t * 128;          // 128 rows x 8 chunks
        int row = idx >> 3, c = idx & 7;
        cpasync16(sb + SM_QF + row * RSTRIDE + c * 16,
                  g_Qf + (bSE + q0 + row) * DK + c * 8);
    }
    load_kv(sb + SM_BUF0, tid, bSE, k0base);
    CP_COMMIT();
    load_kv(sb + SM_BUF0 + SM_BUFSZ, tid, bSE, k0base + BN);
    CP_COMMIT();
    CP_WAIT1();
    __syncthreads();

    // Q fragments: 2 m-tiles per warp (rows wid*32 .. wid*32+31)
    uint32_t qf[2][4][4];
    {
        const uint32_t a0 = (uint32_t)(wid * 32 + (lane & 15)) * RSTRIDE + (uint32_t)(lane >> 4) * 16;
        #pragma unroll
        for (int kc = 0; kc < 4; kc++) {
            ldsm_x4(qf[0][kc], sb + SM_QF + a0 + kc * 32);
            ldsm_x4(qf[1][kc], sb + SM_QF + a0 + 16 * RSTRIDE + kc * 32);
        }
    }

    float O[2][8][4];
    #pragma unroll
    for (int m = 0; m < 2; m++)
        #pragma unroll
        for (int i = 0; i < 8; i++)
            #pragma unroll
            for (int c = 0; c < 4; c++) O[m][i][c] = 0.f;
    float lsum[2][2] = {{0.f, 0.f}, {0.f, 0.f}};

    const uint32_t boff = (uint32_t)(((lane >> 4) & 1) * 8 + (lane & 7)) * RSTRIDE
                        + (uint32_t)((lane >> 3) & 1) * 16;

    const uint32_t bufs[3] = {sb + SM_BUF0, sb + SM_BUF0 + SM_BUFSZ, sb + SM_BUF0 + 2*SM_BUFSZ};

    for (int j = 0; j < NTZ; j++) {
        const uint32_t buf = bufs[j % 3];

        // ---- S = Qf Kf^T, both m-tiles share each K fragment
        float S[2][8][4];
        #pragma unroll
        for (int m = 0; m < 2; m++)
            #pragma unroll
            for (int i = 0; i < 8; i++)
                #pragma unroll
                for (int c = 0; c < 4; c++) S[m][i][c] = 0.f;

        #pragma unroll
        for (int kc = 0; kc < 4; kc++) {
            #pragma unroll
            for (int nph = 0; nph < 2; nph++) {
                uint32_t r0[4], r1[4];
                ldsm_x4(r0, buf + boff + (uint32_t)(2*nph)   * (16 * RSTRIDE) + kc * 32);
                ldsm_x4(r1, buf + boff + (uint32_t)(2*nph+1) * (16 * RSTRIDE) + kc * 32);
                #pragma unroll
                for (int m = 0; m < 2; m++) {
                    mma_f16(S[m][4*nph],   qf[m][kc], r0[0], r0[1]);
                    mma_f16(S[m][4*nph+1], qf[m][kc], r0[2], r0[3]);
                    mma_f16(S[m][4*nph+2], qf[m][kc], r1[0], r1[1]);
                    mma_f16(S[m][4*nph+3], qf[m][kc], r1[2], r1[3]);
                }
            }
        }

        // ---- softmax: pack s to fp16x2, p = ex2.f16x2
        uint32_t Pf[2][4][4];
        #pragma unroll
        for (int m = 0; m < 2; m++) {
            __half2 a0 = __floats2half2_rn(0.f, 0.f);
            __half2 a1 = a0;
            #pragma unroll
            for (int kc2 = 0; kc2 < 4; kc2++) {
                const int nt0 = 2 * kc2, nt1 = nt0 + 1;
                Pf[m][kc2][0] = ex2_h2(pack_h2(S[m][nt0][0], S[m][nt0][1]));
                Pf[m][kc2][1] = ex2_h2(pack_h2(S[m][nt0][2], S[m][nt0][3]));
                Pf[m][kc2][2] = ex2_h2(pack_h2(S[m][nt1][0], S[m][nt1][1]));
                Pf[m][kc2][3] = ex2_h2(pack_h2(S[m][nt1][2], S[m][nt1][3]));
                a0 = __hadd2(a0, __hadd2(u2h2(Pf[m][kc2][0]), u2h2(Pf[m][kc2][2])));
                a1 = __hadd2(a1, __hadd2(u2h2(Pf[m][kc2][1]), u2h2(Pf[m][kc2][3])));
            }
            lsum[m][0] += __low2float(a0) + __high2float(a0);
            lsum[m][1] += __low2float(a1) + __high2float(a1);
        }

        // ---- O += P Vt, both m-tiles share each V fragment
        #pragma unroll
        for (int kc2 = 0; kc2 < 4; kc2++) {
            #pragma unroll
            for (int nph = 0; nph < 2; nph++) {
                uint32_t r0[4], r1[4];
                ldsm_x4(r0, buf + 9216u + boff + (uint32_t)(2*nph)   * (16 * RSTRIDE) + kc2 * 32);
                ldsm_x4(r1, buf + 9216u + boff + (uint32_t)(2*nph+1) * (16 * RSTRIDE) + kc2 * 32);
                #pragma unroll
                for (int m = 0; m < 2; m++) {
                    mma_f16(O[m][4*nph],   Pf[m][kc2], r0[0], r0[1]);
                    mma_f16(O[m][4*nph+1], Pf[m][kc2], r0[2], r0[3]);
                    mma_f16(O[m][4*nph+2], Pf[m][kc2], r1[0], r1[1]);
                    mma_f16(O[m][4*nph+3], Pf[m][kc2], r1[2], r1[3]);
                }
            }
        }

        // ---- pipeline: prefetch j+2, ensure j+1 arrived, one barrier
        if (j + 2 < NTZ) {
            load_kv(bufs[(j + 2) % 3], tid, bSE, k0base + (j + 2) * BN);
            CP_COMMIT();
            CP_WAIT1();
        } else {
            CP_WAIT0();
        }
        __syncthreads();
    }

    // ---- epilogue: reduce row sums, write unnormalized partials
    #pragma unroll
    for (int m = 0; m < 2; m++) {
        lsum[m][0] += __shfl_xor_sync(0xffffffffu, lsum[m][0], 1);
        lsum[m][0] += __shfl_xor_sync(0xffffffffu, lsum[m][0], 2);
        lsum[m][1] += __shfl_xor_sync(0xffffffffu, lsum[m][1], 1);
        lsum[m][1] += __shfl_xor_sync(0xffffffffu, lsum[m][1], 2);

        const int row0 = q0 + wid * 32 + m * 16 + gid;
        float* o0 = g_Op + ((size_t)z * ROWS + bSE + row0) * DK;
        float* o1 = o0 + 8 * DK;
        if (tq == 0) {
            g_lp[(size_t)z * ROWS + bSE + row0]     = lsum[m][0];
            g_lp[(size_t)z * ROWS + bSE + row0 + 8] = lsum[m][1];
        }
        #pragma unroll
        for (int nt = 0; nt < 8; nt++) {
            const int col = nt * 8 + 2 * tq;
            *(float2*)(o0 + col) = make_float2(O[m][nt][0], O[m][nt][1]);
            *(float2*)(o1 + col) = make_float2(O[m][nt][2], O[m][nt][3]);
        }
    }
}

// ---------------------------------------------------------------------------
// Combine: out = (O0 + O1) / (l0 + l1)  (round-8 form: 1 float4/thread)
// ---------------------------------------------------------------------------
__global__ __launch_bounds__(256) void combine(float* __restrict__ out)
{
    const int idx = blockIdx.x * 256 + threadIdx.x;   // float4 index, 16/row
    const int row = idx >> 4;
    const float inv = 1.f / (g_lp[row] + g_lp[ROWS + row]);
    const float4 a = ((const float4*)g_Op)[idx];
    const float4 b = ((const float4*)g_Op)[idx + (ROWS * DK / 4)];
    float4 r;
    r.x = (a.x + b.x) * inv;
    r.y = (a.y + b.y) * inv;
    r.z = (a.z + b.z) * inv;
    r.w = (a.w + b.w) * inv;
    ((float4*)out)[idx] = r;
}

// ---------------------------------------------------------------------------
extern "C" void kernel_launch(void* const* d_in, const int* in_sizes, int n_in,
                              void* d_out, int out_size)
{
    const float* X  = (const float*)d_in[0];
    // d_in[1] cultural_embedding, d_in[8..10] WC,bC,lam: softmax-invariant -> unused
    const float* WQ = (const float*)d_in[2];
    const float* bQ = (const float*)d_in[3];
    const float* WK = (const float*)d_in[4];
    const float* bK = (const float*)d_in[5];
    const float* WV = (const float*)d_in[6];
    const float* bV = (const float*)d_in[7];
    float* out = (float*)d_out;

    cudaFuncSetAttribute(proj_tc,   cudaFuncAttributeMaxDynamicSharedMemorySize, P_TOTAL);
    cudaFuncSetAttribute(flash_mma, cudaFuncAttributeMaxDynamicSharedMemorySize, SM_TOTAL);

    prep_all<<<256 + XCONV_BLKS, 256>>>(X, WQ, bQ, WK, bK, WV, bV);
    proj_tc<<<dim3(ROWS / 128, 2), 128, P_TOTAL>>>();
    flash_mma<<<dim3(SEQ / BM, BATCH, NZ), 128, SM_TOTAL>>>();
    combine<<<ROWS * DK / 4 / 256, 256>>>(out);
}